// round 2
// baseline (speedup 1.0000x reference)
#include <cuda_runtime.h>
#include <cstdint>
#include <cstddef>

#define NN 100000
#define EE 1600000
#define HD 128

// Scratch (allocations are forbidden; __device__ globals are the sanctioned path)
__device__ float g_h[(size_t)NN * HD];
__device__ float g_agg[(size_t)NN * HD];

__device__ __forceinline__ float sigmoidf_(float x) { return 1.0f / (1.0f + expf(-x)); }
__device__ __forceinline__ float softplusf_(float x) {
    // numerically stable: max(x,0) + log1p(exp(-|x|))
    return fmaxf(x, 0.0f) + log1pf(expf(-fabsf(x)));
}

// ---------------------------------------------------------------------------
// Weight tile loader: stages rows [row_base, row_base+128) x cols [kofs, kofs+32)
// of row-major W (leading dim ldw) into WS in k-major layout WS[k*132 + j].
// ---------------------------------------------------------------------------
__device__ __forceinline__ void load_wtile(float* WS, const float* __restrict__ W,
                                           int row_base, int ldw, int kofs, int tid) {
    const int q  = tid & 7;    // k4 index 0..7
    const int jj = tid >> 3;   // 0..31
#pragma unroll
    for (int r = 0; r < 4; ++r) {
        const int j = jj + r * 32;  // 0..127
        const float4 w = *reinterpret_cast<const float4*>(
            W + (size_t)(row_base + j) * ldw + kofs + q * 4);
        WS[(q * 4 + 0) * 132 + j] = w.x;
        WS[(q * 4 + 1) * 132 + j] = w.y;
        WS[(q * 4 + 2) * 132 + j] = w.z;
        WS[(q * 4 + 3) * 132 + j] = w.w;
    }
}

// ---------------------------------------------------------------------------
// 32-k MMA micro-tile: acc[4 nodes][4 outs] += A[i0..i0+3][aofs..aofs+31] * WS^T
// ---------------------------------------------------------------------------
__device__ __forceinline__ void mma_tile(float acc[4][4], const float* WS,
                                         const float* A, int lda, int aofs,
                                         int i0, int j0) {
#pragma unroll
    for (int k4 = 0; k4 < 8; ++k4) {
        float4 wv[4];
#pragma unroll
        for (int t = 0; t < 4; ++t)
            wv[t] = *reinterpret_cast<const float4*>(WS + (k4 * 4 + t) * 132 + j0);
#pragma unroll
        for (int u = 0; u < 4; ++u) {
            const float4 av = *reinterpret_cast<const float4*>(
                A + (i0 + u) * lda + aofs + k4 * 4);
            acc[u][0] = fmaf(av.x, wv[0].x, acc[u][0]);
            acc[u][1] = fmaf(av.x, wv[0].y, acc[u][1]);
            acc[u][2] = fmaf(av.x, wv[0].z, acc[u][2]);
            acc[u][3] = fmaf(av.x, wv[0].w, acc[u][3]);
            acc[u][0] = fmaf(av.y, wv[1].x, acc[u][0]);
            acc[u][1] = fmaf(av.y, wv[1].y, acc[u][1]);
            acc[u][2] = fmaf(av.y, wv[1].z, acc[u][2]);
            acc[u][3] = fmaf(av.y, wv[1].w, acc[u][3]);
            acc[u][0] = fmaf(av.z, wv[2].x, acc[u][0]);
            acc[u][1] = fmaf(av.z, wv[2].y, acc[u][1]);
            acc[u][2] = fmaf(av.z, wv[2].z, acc[u][2]);
            acc[u][3] = fmaf(av.z, wv[2].w, acc[u][3]);
            acc[u][0] = fmaf(av.w, wv[3].x, acc[u][0]);
            acc[u][1] = fmaf(av.w, wv[3].y, acc[u][1]);
            acc[u][2] = fmaf(av.w, wv[3].z, acc[u][2]);
            acc[u][3] = fmaf(av.w, wv[3].w, acc[u][3]);
        }
    }
}

// ---------------------------------------------------------------------------
// h0 = relu(x @ W_in^T + b_in)
// ---------------------------------------------------------------------------
__global__ __launch_bounds__(256, 2) void in_gemm_kernel(const float* __restrict__ x,
                                                         const float* __restrict__ W,
                                                         const float* __restrict__ b,
                                                         float* __restrict__ hout) {
    __shared__ float X[32 * 128];
    __shared__ float WS[32 * 132];
    const int tid = threadIdx.x;
    const int node0 = blockIdx.x * 32;
    const int jg = tid & 31, ig = tid >> 5;
    const int j0 = jg * 4, i0 = ig * 4;

    for (int t = tid; t < 1024; t += 256) {
        const int i = t >> 5, c = t & 31;
        reinterpret_cast<float4*>(X + i * 128)[c] =
            reinterpret_cast<const float4*>(x + (size_t)(node0 + i) * HD)[c];
    }

    float acc[4][4];
#pragma unroll
    for (int u = 0; u < 4; ++u)
#pragma unroll
        for (int v = 0; v < 4; ++v) acc[u][v] = b[j0 + v];

    for (int kt = 0; kt < 4; ++kt) {
        __syncthreads();
        load_wtile(WS, W, 0, 128, kt * 32, tid);
        __syncthreads();
        mma_tile(acc, WS, X, 128, kt * 32, i0, j0);
    }

#pragma unroll
    for (int u = 0; u < 4; ++u) {
        float4 o;
        o.x = fmaxf(acc[u][0], 0.0f);
        o.y = fmaxf(acc[u][1], 0.0f);
        o.z = fmaxf(acc[u][2], 0.0f);
        o.w = fmaxf(acc[u][3], 0.0f);
        *reinterpret_cast<float4*>(hout + (size_t)(node0 + i0 + u) * HD + j0) = o;
    }
}

// ---------------------------------------------------------------------------
// agg = 0
// ---------------------------------------------------------------------------
__global__ void zero_kernel(float4* __restrict__ p) {
    p[(size_t)blockIdx.x * 256 + threadIdx.x] = make_float4(0.f, 0.f, 0.f, 0.f);
}

// ---------------------------------------------------------------------------
// agg[row] += |h[row] - h[col]|   (warp per edge, vector atomics)
// edge_index is INT32: JAX's default x64-disabled config downgrades the
// reference's jnp.int64 randint to int32.
// ---------------------------------------------------------------------------
__global__ __launch_bounds__(256) void edge_kernel(const float* __restrict__ h,
                                                   const int* __restrict__ ei,
                                                   float* __restrict__ agg) {
    const int w = blockIdx.x * 8 + (threadIdx.x >> 5);
    const int lane = threadIdx.x & 31;
    const int r = ei[w];
    const int c = ei[EE + w];
    const float4 a = reinterpret_cast<const float4*>(h + (size_t)r * HD)[lane];
    const float4 b = reinterpret_cast<const float4*>(h + (size_t)c * HD)[lane];
    const float dx = fabsf(a.x - b.x);
    const float dy = fabsf(a.y - b.y);
    const float dz = fabsf(a.z - b.z);
    const float dw = fabsf(a.w - b.w);
    float* p = agg + (size_t)r * HD + lane * 4;
    asm volatile("red.global.add.v4.f32 [%0], {%1,%2,%3,%4};"
                 :: "l"(p), "f"(dx), "f"(dy), "f"(dz), "f"(dw)
                 : "memory");
}

// ---------------------------------------------------------------------------
// Fused per-layer node kernel:
//   hw  = relu([h, agg] @ Wd^T + bd)
//   tau = softplus(hw @ Wt^T + bt)
//   GRU(agg, hw) -> h_new where tau < 0.005 else hw  (mask == tau<thr, since
//   tau<0.005 implies floor(1/tau) >= 200 -> min(.,10)=10 > 0)
// Block: 256 threads, 32 nodes. In-place update of h.
// ---------------------------------------------------------------------------
__global__ __launch_bounds__(256, 2) void node_kernel(
    float* __restrict__ h, const float* __restrict__ agg,
    const float* __restrict__ Wd, const float* __restrict__ bd,
    const float* __restrict__ Wt, const float* __restrict__ bt,
    const float* __restrict__ Wih, const float* __restrict__ Whh,
    const float* __restrict__ bih, const float* __restrict__ bhh,
    float* __restrict__ tau_out) {
    extern __shared__ float sm[];
    float* HA  = sm;              // [32][256]  h | agg concat
    float* HW  = HA + 32 * 256;   // [32][132]  new h after Wd layer
    float* WS  = HW + 32 * 132;   // [32][132]  weight k-tile
    float* WT  = WS + 32 * 132;   // [128]
    float* TAU = WT + 128;        // [32]

    const int tid = threadIdx.x;
    const int node0 = blockIdx.x * 32;
    const int jg = tid & 31, ig = tid >> 5;
    const int j0 = jg * 4, i0 = ig * 4;

    for (int t = tid; t < 1024; t += 256) {
        const int i = t >> 5, c = t & 31;
        reinterpret_cast<float4*>(HA + i * 256)[c] =
            reinterpret_cast<const float4*>(h + (size_t)(node0 + i) * HD)[c];
        reinterpret_cast<float4*>(HA + i * 256 + 128)[c] =
            reinterpret_cast<const float4*>(agg + (size_t)(node0 + i) * HD)[c];
    }
    if (tid < 128) WT[tid] = Wt[tid];

    // ---- phase 1: hw = relu([h,agg] @ Wd^T + bd) ----
    float acc[4][4];
#pragma unroll
    for (int u = 0; u < 4; ++u)
#pragma unroll
        for (int v = 0; v < 4; ++v) acc[u][v] = bd[j0 + v];

    for (int kt = 0; kt < 8; ++kt) {
        __syncthreads();
        load_wtile(WS, Wd, 0, 256, kt * 32, tid);
        __syncthreads();
        mma_tile(acc, WS, HA, 256, kt * 32, i0, j0);
    }
#pragma unroll
    for (int u = 0; u < 4; ++u) {
        float4 o;
        o.x = fmaxf(acc[u][0], 0.0f);
        o.y = fmaxf(acc[u][1], 0.0f);
        o.z = fmaxf(acc[u][2], 0.0f);
        o.w = fmaxf(acc[u][3], 0.0f);
        *reinterpret_cast<float4*>(HW + (i0 + u) * 132 + j0) = o;
    }
    __syncthreads();

    // ---- phase 2: tau = softplus(hw @ Wt^T + bt) ----
    {
        const int lane = jg;
#pragma unroll
        for (int u = 0; u < 4; ++u) {
            const int i = i0 + u;
            float s = HW[i * 132 + lane]      * WT[lane] +
                      HW[i * 132 + lane + 32] * WT[lane + 32] +
                      HW[i * 132 + lane + 64] * WT[lane + 64] +
                      HW[i * 132 + lane + 96] * WT[lane + 96];
#pragma unroll
            for (int o = 16; o > 0; o >>= 1) s += __shfl_xor_sync(0xffffffffu, s, o);
            if (lane == 0) {
                const float tv = softplusf_(s + bt[0]);
                TAU[i] = tv;
                if (tau_out) tau_out[node0 + i] = tv;
            }
        }
    }
    // TAU written by the same warp that reads it in the mt==2 epilogue; no extra
    // sync needed beyond the kt-loop __syncthreads.

    // ---- phase 3: GRU(agg, hw), masked ----
    float rg[4][4], zg[4][4];
    for (int mt = 0; mt < 3; ++mt) {
        float ai[4][4], ah[4][4];
#pragma unroll
        for (int u = 0; u < 4; ++u)
#pragma unroll
            for (int v = 0; v < 4; ++v) {
                ai[u][v] = bih[mt * 128 + j0 + v];
                ah[u][v] = bhh[mt * 128 + j0 + v];
            }
        for (int kt = 0; kt < 4; ++kt) {  // gi: agg @ W_ih^T
            __syncthreads();
            load_wtile(WS, Wih, mt * 128, 128, kt * 32, tid);
            __syncthreads();
            mma_tile(ai, WS, HA, 256, 128 + kt * 32, i0, j0);
        }
        for (int kt = 0; kt < 4; ++kt) {  // gh: hw @ W_hh^T
            __syncthreads();
            load_wtile(WS, Whh, mt * 128, 128, kt * 32, tid);
            __syncthreads();
            mma_tile(ah, WS, HW, 132, kt * 32, i0, j0);
        }
        if (mt == 0) {
#pragma unroll
            for (int u = 0; u < 4; ++u)
#pragma unroll
                for (int v = 0; v < 4; ++v) rg[u][v] = sigmoidf_(ai[u][v] + ah[u][v]);
        } else if (mt == 1) {
#pragma unroll
            for (int u = 0; u < 4; ++u)
#pragma unroll
                for (int v = 0; v < 4; ++v) zg[u][v] = sigmoidf_(ai[u][v] + ah[u][v]);
        } else {
#pragma unroll
            for (int u = 0; u < 4; ++u) {
                const float4 hw4 = *reinterpret_cast<const float4*>(HW + (i0 + u) * 132 + j0);
                const float hwv[4] = {hw4.x, hw4.y, hw4.z, hw4.w};
                const bool msk = TAU[i0 + u] < 0.005f;
                float ov[4];
#pragma unroll
                for (int v = 0; v < 4; ++v) {
                    const float n = tanhf(ai[u][v] + rg[u][v] * ah[u][v]);
                    const float hn = (1.0f - zg[u][v]) * n + zg[u][v] * hwv[v];
                    ov[v] = msk ? hn : hwv[v];
                }
                *reinterpret_cast<float4*>(h + (size_t)(node0 + i0 + u) * HD + j0) =
                    make_float4(ov[0], ov[1], ov[2], ov[3]);
            }
        }
    }
}

// ---------------------------------------------------------------------------
// out = h @ Wo^T + bo   (warp per node)
// ---------------------------------------------------------------------------
__global__ __launch_bounds__(256) void out_kernel(const float* __restrict__ h,
                                                  const float* __restrict__ Wo,
                                                  const float* __restrict__ bo,
                                                  float* __restrict__ out) {
    const int nid = blockIdx.x * 8 + (threadIdx.x >> 5);
    const int lane = threadIdx.x & 31;
    float a0 = 0.f, a1 = 0.f;
#pragma unroll
    for (int t = 0; t < 4; ++t) {
        const float hv = h[(size_t)nid * HD + lane + t * 32];
        a0 = fmaf(hv, Wo[lane + t * 32], a0);
        a1 = fmaf(hv, Wo[HD + lane + t * 32], a1);
    }
#pragma unroll
    for (int o = 16; o > 0; o >>= 1) {
        a0 += __shfl_xor_sync(0xffffffffu, a0, o);
        a1 += __shfl_xor_sync(0xffffffffu, a1, o);
    }
    if (lane == 0) {
        out[(size_t)nid * 2 + 0] = a0 + bo[0];
        out[(size_t)nid * 2 + 1] = a1 + bo[1];
    }
}

// ---------------------------------------------------------------------------
extern "C" void kernel_launch(void* const* d_in, const int* in_sizes, int n_in,
                              void* d_out, int out_size) {
    const float* x    = (const float*)d_in[0];
    const int*   ei   = (const int*)d_in[1];   // int32 (JAX x64-disabled)
    const float* W_in = (const float*)d_in[2];
    const float* b_in = (const float*)d_in[3];
    const float* Wd   = (const float*)d_in[4];
    const float* bd   = (const float*)d_in[5];
    const float* Wt   = (const float*)d_in[6];
    const float* bt   = (const float*)d_in[7];
    const float* Wih  = (const float*)d_in[8];
    const float* Whh  = (const float*)d_in[9];
    const float* bih  = (const float*)d_in[10];
    const float* bhh  = (const float*)d_in[11];
    const float* Wo   = (const float*)d_in[12];
    const float* bo   = (const float*)d_in[13];

    float* out = (float*)d_out;
    float* tau_out = (out_size >= NN * 3) ? out + (size_t)NN * 2 : nullptr;

    float *h, *agg;
    cudaGetSymbolAddress((void**)&h, g_h);
    cudaGetSymbolAddress((void**)&agg, g_agg);

    const size_t smem_node = (32 * 256 + 32 * 132 + 32 * 132 + 128 + 32) * sizeof(float);
    cudaFuncSetAttribute(node_kernel, cudaFuncAttributeMaxDynamicSharedMemorySize,
                         (int)smem_node);

    in_gemm_kernel<<<NN / 32, 256>>>(x, W_in, b_in, h);

    for (int l = 0; l < 2; ++l) {
        zero_kernel<<<(NN * HD) / (256 * 4), 256>>>((float4*)agg);
        edge_kernel<<<EE / 8, 256>>>(h, ei, agg);
        node_kernel<<<NN / 32, 256, smem_node>>>(
            h, agg, Wd + (size_t)l * HD * 2 * HD, bd + (size_t)l * HD,
            Wt, bt, Wih, Whh, bih, bhh, (l == 1) ? tau_out : nullptr);
    }

    out_kernel<<<NN / 8, 256>>>(h, Wo, bo, out);
}

// round 3
// speedup vs baseline: 2.0117x; 2.0117x over previous
#include <cuda_runtime.h>
#include <cstdint>
#include <cstddef>

#define NN 100000
#define EE 1600000
#define HD 128

// Scratch (allocations are forbidden; __device__ globals are the sanctioned path)
__device__ float g_h[(size_t)NN * HD];
__device__ float g_agg[(size_t)NN * HD];

__device__ __forceinline__ float sigmoidf_(float x) { return 1.0f / (1.0f + expf(-x)); }
__device__ __forceinline__ float softplusf_(float x) {
    return fmaxf(x, 0.0f) + log1pf(expf(-fabsf(x)));
}

// ---------------------------------------------------------------------------
// Weight tile loader: rows [row_base, row_base+128) x cols [kofs, kofs+32) of
// row-major W (ld=ldw) into WS k-major: WS[k*132 + j].
// ---------------------------------------------------------------------------
__device__ __forceinline__ void load_wtile(float* WS, const float* __restrict__ W,
                                           int row_base, int ldw, int kofs, int tid) {
    const int q  = tid & 7;
    const int jj = tid >> 3;
#pragma unroll
    for (int r = 0; r < 4; ++r) {
        const int j = jj + r * 32;
        const float4 w = *reinterpret_cast<const float4*>(
            W + (size_t)(row_base + j) * ldw + kofs + q * 4);
        WS[(q * 4 + 0) * 132 + j] = w.x;
        WS[(q * 4 + 1) * 132 + j] = w.y;
        WS[(q * 4 + 2) * 132 + j] = w.z;
        WS[(q * 4 + 3) * 132 + j] = w.w;
    }
}

// ---------------------------------------------------------------------------
// 32-k MMA micro-tile: acc[4 nodes][4 outs] += A[i0..i0+3][aofs..+31] * WS^T
// ---------------------------------------------------------------------------
__device__ __forceinline__ void mma_tile(float acc[4][4], const float* WS,
                                         const float* A, int lda, int aofs,
                                         int i0, int j0) {
#pragma unroll
    for (int k4 = 0; k4 < 8; ++k4) {
        float4 wv[4];
#pragma unroll
        for (int t = 0; t < 4; ++t)
            wv[t] = *reinterpret_cast<const float4*>(WS + (k4 * 4 + t) * 132 + j0);
#pragma unroll
        for (int u = 0; u < 4; ++u) {
            const float4 av = *reinterpret_cast<const float4*>(
                A + (i0 + u) * lda + aofs + k4 * 4);
            acc[u][0] = fmaf(av.x, wv[0].x, acc[u][0]);
            acc[u][1] = fmaf(av.x, wv[0].y, acc[u][1]);
            acc[u][2] = fmaf(av.x, wv[0].z, acc[u][2]);
            acc[u][3] = fmaf(av.x, wv[0].w, acc[u][3]);
            acc[u][0] = fmaf(av.y, wv[1].x, acc[u][0]);
            acc[u][1] = fmaf(av.y, wv[1].y, acc[u][1]);
            acc[u][2] = fmaf(av.y, wv[1].z, acc[u][2]);
            acc[u][3] = fmaf(av.y, wv[1].w, acc[u][3]);
            acc[u][0] = fmaf(av.z, wv[2].x, acc[u][0]);
            acc[u][1] = fmaf(av.z, wv[2].y, acc[u][1]);
            acc[u][2] = fmaf(av.z, wv[2].z, acc[u][2]);
            acc[u][3] = fmaf(av.z, wv[2].w, acc[u][3]);
            acc[u][0] = fmaf(av.w, wv[3].x, acc[u][0]);
            acc[u][1] = fmaf(av.w, wv[3].y, acc[u][1]);
            acc[u][2] = fmaf(av.w, wv[3].z, acc[u][2]);
            acc[u][3] = fmaf(av.w, wv[3].w, acc[u][3]);
        }
    }
}

// ---------------------------------------------------------------------------
// h0 = relu(x @ W_in^T + b_in)
// ---------------------------------------------------------------------------
__global__ __launch_bounds__(256, 2) void in_gemm_kernel(const float* __restrict__ x,
                                                         const float* __restrict__ W,
                                                         const float* __restrict__ b,
                                                         float* __restrict__ hout) {
    __shared__ float X[32 * 128];
    __shared__ float WS[32 * 132];
    const int tid = threadIdx.x;
    const int node0 = blockIdx.x * 32;
    const int jg = tid & 31, ig = tid >> 5;
    const int j0 = jg * 4, i0 = ig * 4;

    for (int t = tid; t < 1024; t += 256) {
        const int i = t >> 5, c = t & 31;
        reinterpret_cast<float4*>(X + i * 128)[c] =
            reinterpret_cast<const float4*>(x + (size_t)(node0 + i) * HD)[c];
    }

    float acc[4][4];
#pragma unroll
    for (int u = 0; u < 4; ++u)
#pragma unroll
        for (int v = 0; v < 4; ++v) acc[u][v] = b[j0 + v];

    for (int kt = 0; kt < 4; ++kt) {
        __syncthreads();
        load_wtile(WS, W, 0, 128, kt * 32, tid);
        __syncthreads();
        mma_tile(acc, WS, X, 128, kt * 32, i0, j0);
    }

#pragma unroll
    for (int u = 0; u < 4; ++u) {
        float4 o;
        o.x = fmaxf(acc[u][0], 0.0f);
        o.y = fmaxf(acc[u][1], 0.0f);
        o.z = fmaxf(acc[u][2], 0.0f);
        o.w = fmaxf(acc[u][3], 0.0f);
        *reinterpret_cast<float4*>(hout + (size_t)(node0 + i0 + u) * HD + j0) = o;
    }
}

// ---------------------------------------------------------------------------
__global__ void zero_kernel(float4* __restrict__ p) {
    p[(size_t)blockIdx.x * 256 + threadIdx.x] = make_float4(0.f, 0.f, 0.f, 0.f);
}

// ---------------------------------------------------------------------------
// agg[row] += |h[row] - h[col]|   (warp per edge, vector reduction atomics)
// ---------------------------------------------------------------------------
__global__ __launch_bounds__(256) void edge_kernel(const float* __restrict__ h,
                                                   const int* __restrict__ ei,
                                                   float* __restrict__ agg) {
    const int w = blockIdx.x * 8 + (threadIdx.x >> 5);
    const int lane = threadIdx.x & 31;
    const int r = ei[w];
    const int c = ei[EE + w];
    const float4 a = reinterpret_cast<const float4*>(h + (size_t)r * HD)[lane];
    const float4 b = reinterpret_cast<const float4*>(h + (size_t)c * HD)[lane];
    const float dx = fabsf(a.x - b.x);
    const float dy = fabsf(a.y - b.y);
    const float dz = fabsf(a.z - b.z);
    const float dw = fabsf(a.w - b.w);
    float* p = agg + (size_t)r * HD + lane * 4;
    asm volatile("red.global.add.v4.f32 [%0], {%1,%2,%3,%4};"
                 :: "l"(p), "f"(dx), "f"(dy), "f"(dz), "f"(dw)
                 : "memory");
}

// ---------------------------------------------------------------------------
// Fused per-layer node kernel:
//   hw  = relu([h, agg] @ Wd^T + bd)
//   tau = softplus(hw @ Wt^T + bt)
//   if any node in this 32-node block has tau < 0.005: masked GRU (exact)
//   else: h = hw  (GRU output is unused -> skip 75% of the FLOPs)
// ---------------------------------------------------------------------------
__global__ __launch_bounds__(256, 2) void node_kernel(
    float* __restrict__ h, const float* __restrict__ agg,
    const float* __restrict__ Wd, const float* __restrict__ bd,
    const float* __restrict__ Wt, const float* __restrict__ bt,
    const float* __restrict__ Wih, const float* __restrict__ Whh,
    const float* __restrict__ bih, const float* __restrict__ bhh,
    float* __restrict__ tau_out) {
    extern __shared__ float sm[];
    float* HA  = sm;              // [32][256]  h | agg concat
    float* HW  = HA + 32 * 256;   // [32][132]
    float* WS  = HW + 32 * 132;   // [32][132]
    float* WT  = WS + 32 * 132;   // [128]
    float* TAU = WT + 128;        // [32]
    __shared__ int anyMask;

    const int tid = threadIdx.x;
    const int node0 = blockIdx.x * 32;
    const int jg = tid & 31, ig = tid >> 5;
    const int j0 = jg * 4, i0 = ig * 4;

    if (tid == 0) anyMask = 0;

    for (int t = tid; t < 1024; t += 256) {
        const int i = t >> 5, c = t & 31;
        reinterpret_cast<float4*>(HA + i * 256)[c] =
            reinterpret_cast<const float4*>(h + (size_t)(node0 + i) * HD)[c];
        reinterpret_cast<float4*>(HA + i * 256 + 128)[c] =
            reinterpret_cast<const float4*>(agg + (size_t)(node0 + i) * HD)[c];
    }
    if (tid < 128) WT[tid] = Wt[tid];

    // ---- phase 1: hw = relu([h,agg] @ Wd^T + bd) ----
    float acc[4][4];
#pragma unroll
    for (int u = 0; u < 4; ++u)
#pragma unroll
        for (int v = 0; v < 4; ++v) acc[u][v] = bd[j0 + v];

    for (int kt = 0; kt < 8; ++kt) {
        __syncthreads();
        load_wtile(WS, Wd, 0, 256, kt * 32, tid);
        __syncthreads();
        mma_tile(acc, WS, HA, 256, kt * 32, i0, j0);
    }
#pragma unroll
    for (int u = 0; u < 4; ++u) {
        float4 o;
        o.x = fmaxf(acc[u][0], 0.0f);
        o.y = fmaxf(acc[u][1], 0.0f);
        o.z = fmaxf(acc[u][2], 0.0f);
        o.w = fmaxf(acc[u][3], 0.0f);
        *reinterpret_cast<float4*>(HW + (i0 + u) * 132 + j0) = o;
    }
    __syncthreads();

    // ---- phase 2: tau = softplus(hw @ Wt^T + bt); detect masked nodes ----
    {
        const int lane = jg;
#pragma unroll
        for (int u = 0; u < 4; ++u) {
            const int i = i0 + u;
            float s = HW[i * 132 + lane]      * WT[lane] +
                      HW[i * 132 + lane + 32] * WT[lane + 32] +
                      HW[i * 132 + lane + 64] * WT[lane + 64] +
                      HW[i * 132 + lane + 96] * WT[lane + 96];
#pragma unroll
            for (int o = 16; o > 0; o >>= 1) s += __shfl_xor_sync(0xffffffffu, s, o);
            if (lane == 0) {
                const float tv = softplusf_(s + bt[0]);
                TAU[i] = tv;
                if (tau_out) tau_out[node0 + i] = tv;
                if (tv < 0.005f) anyMask = 1;  // benign same-value race
            }
        }
    }
    __syncthreads();

    // ---- common case: no masked node in this block -> h = hw, done ----
    if (anyMask == 0) {
#pragma unroll
        for (int u = 0; u < 4; ++u) {
            const float4 hw4 = *reinterpret_cast<const float4*>(HW + (i0 + u) * 132 + j0);
            *reinterpret_cast<float4*>(h + (size_t)(node0 + i0 + u) * HD + j0) = hw4;
        }
        return;
    }

    // ---- rare path: full masked GRU(agg, hw) ----
    float rg[4][4], zg[4][4];
    for (int mt = 0; mt < 3; ++mt) {
        float ai[4][4], ah[4][4];
#pragma unroll
        for (int u = 0; u < 4; ++u)
#pragma unroll
            for (int v = 0; v < 4; ++v) {
                ai[u][v] = bih[mt * 128 + j0 + v];
                ah[u][v] = bhh[mt * 128 + j0 + v];
            }
        for (int kt = 0; kt < 4; ++kt) {
            __syncthreads();
            load_wtile(WS, Wih, mt * 128, 128, kt * 32, tid);
            __syncthreads();
            mma_tile(ai, WS, HA, 256, 128 + kt * 32, i0, j0);
        }
        for (int kt = 0; kt < 4; ++kt) {
            __syncthreads();
            load_wtile(WS, Whh, mt * 128, 128, kt * 32, tid);
            __syncthreads();
            mma_tile(ah, WS, HW, 132, kt * 32, i0, j0);
        }
        if (mt == 0) {
#pragma unroll
            for (int u = 0; u < 4; ++u)
#pragma unroll
                for (int v = 0; v < 4; ++v) rg[u][v] = sigmoidf_(ai[u][v] + ah[u][v]);
        } else if (mt == 1) {
#pragma unroll
            for (int u = 0; u < 4; ++u)
#pragma unroll
                for (int v = 0; v < 4; ++v) zg[u][v] = sigmoidf_(ai[u][v] + ah[u][v]);
        } else {
#pragma unroll
            for (int u = 0; u < 4; ++u) {
                const float4 hw4 = *reinterpret_cast<const float4*>(HW + (i0 + u) * 132 + j0);
                const float hwv[4] = {hw4.x, hw4.y, hw4.z, hw4.w};
                const bool msk = TAU[i0 + u] < 0.005f;
                float ov[4];
#pragma unroll
                for (int v = 0; v < 4; ++v) {
                    const float n = tanhf(ai[u][v] + rg[u][v] * ah[u][v]);
                    const float hn = (1.0f - zg[u][v]) * n + zg[u][v] * hwv[v];
                    ov[v] = msk ? hn : hwv[v];
                }
                *reinterpret_cast<float4*>(h + (size_t)(node0 + i0 + u) * HD + j0) =
                    make_float4(ov[0], ov[1], ov[2], ov[3]);
            }
        }
    }
}

// ---------------------------------------------------------------------------
// out = h @ Wo^T + bo   (warp per node)
// ---------------------------------------------------------------------------
__global__ __launch_bounds__(256) void out_kernel(const float* __restrict__ h,
                                                  const float* __restrict__ Wo,
                                                  const float* __restrict__ bo,
                                                  float* __restrict__ out) {
    const int nid = blockIdx.x * 8 + (threadIdx.x >> 5);
    const int lane = threadIdx.x & 31;
    float a0 = 0.f, a1 = 0.f;
#pragma unroll
    for (int t = 0; t < 4; ++t) {
        const float hv = h[(size_t)nid * HD + lane + t * 32];
        a0 = fmaf(hv, Wo[lane + t * 32], a0);
        a1 = fmaf(hv, Wo[HD + lane + t * 32], a1);
    }
#pragma unroll
    for (int o = 16; o > 0; o >>= 1) {
        a0 += __shfl_xor_sync(0xffffffffu, a0, o);
        a1 += __shfl_xor_sync(0xffffffffu, a1, o);
    }
    if (lane == 0) {
        out[(size_t)nid * 2 + 0] = a0 + bo[0];
        out[(size_t)nid * 2 + 1] = a1 + bo[1];
    }
}

// ---------------------------------------------------------------------------
extern "C" void kernel_launch(void* const* d_in, const int* in_sizes, int n_in,
                              void* d_out, int out_size) {
    const float* x    = (const float*)d_in[0];
    const int*   ei   = (const int*)d_in[1];   // int32 (JAX x64-disabled)
    const float* W_in = (const float*)d_in[2];
    const float* b_in = (const float*)d_in[3];
    const float* Wd   = (const float*)d_in[4];
    const float* bd   = (const float*)d_in[5];
    const float* Wt   = (const float*)d_in[6];
    const float* bt   = (const float*)d_in[7];
    const float* Wih  = (const float*)d_in[8];
    const float* Whh  = (const float*)d_in[9];
    const float* bih  = (const float*)d_in[10];
    const float* bhh  = (const float*)d_in[11];
    const float* Wo   = (const float*)d_in[12];
    const float* bo   = (const float*)d_in[13];

    float* out = (float*)d_out;
    float* tau_out = (out_size >= NN * 3) ? out + (size_t)NN * 2 : nullptr;

    float *h, *agg;
    cudaGetSymbolAddress((void**)&h, g_h);
    cudaGetSymbolAddress((void**)&agg, g_agg);

    const size_t smem_node = (32 * 256 + 32 * 132 + 32 * 132 + 128 + 32) * sizeof(float);
    cudaFuncSetAttribute(node_kernel, cudaFuncAttributeMaxDynamicSharedMemorySize,
                         (int)smem_node);

    in_gemm_kernel<<<NN / 32, 256>>>(x, W_in, b_in, h);

    for (int l = 0; l < 2; ++l) {
        zero_kernel<<<(NN * HD) / (256 * 4), 256>>>((float4*)agg);
        edge_kernel<<<EE / 8, 256>>>(h, ei, agg);
        node_kernel<<<NN / 32, 256, smem_node>>>(
            h, agg, Wd + (size_t)l * HD * 2 * HD, bd + (size_t)l * HD,
            Wt, bt, Wih, Whh, bih, bhh, (l == 1) ? tau_out : nullptr);
    }

    out_kernel<<<NN / 8, 256>>>(h, Wo, bo, out);
}

// round 4
// speedup vs baseline: 2.1748x; 1.0811x over previous
#include <cuda_runtime.h>
#include <cstdint>
#include <cstddef>

#define NN 100000
#define EE 1600000
#define HD 128

typedef unsigned long long ull;

// Scratch (__device__ globals; allocations forbidden)
__device__ float g_h[(size_t)NN * HD];
__device__ float g_agg[(size_t)NN * HD];
__device__ int   g_cnt[NN];
__device__ int   g_rowptr[NN + 1];
__device__ int   g_wr[NN];
__device__ int   g_col[EE];

__device__ __forceinline__ float sigmoidf_(float x) { return 1.0f / (1.0f + expf(-x)); }
__device__ __forceinline__ float softplusf_(float x) {
    return fmaxf(x, 0.0f) + log1pf(expf(-fabsf(x)));
}

// ---- packed f32x2 helpers (FFMA2 is only reachable via PTX) ----
__device__ __forceinline__ ull splat2(float x) {
    ull r; asm("mov.b64 %0, {%1, %1};" : "=l"(r) : "f"(x)); return r;
}
__device__ __forceinline__ ull pack2(float lo, float hi) {
    ull r; asm("mov.b64 %0, {%1, %2};" : "=l"(r) : "f"(lo), "f"(hi)); return r;
}
__device__ __forceinline__ void unpack2(float& lo, float& hi, ull v) {
    asm("mov.b64 {%0, %1}, %2;" : "=f"(lo), "=f"(hi) : "l"(v));
}
__device__ __forceinline__ void fma2(ull& d, ull a, ull b) {
    asm("fma.rn.f32x2 %0, %1, %2, %3;" : "=l"(d) : "l"(a), "l"(b), "l"(d));
}

// ---------------------------------------------------------------------------
// Weight tile loader (128 threads): rows [row_base, +128) x cols [kofs, +32)
// of row-major W (ld=ldw) into WS k-major: WS[k*132 + j].
// ---------------------------------------------------------------------------
__device__ __forceinline__ void load_wtile(float* WS, const float* __restrict__ W,
                                           int row_base, int ldw, int kofs, int tid) {
    const int q  = tid & 7;    // k4 0..7
    const int jj = tid >> 3;   // 0..15
#pragma unroll
    for (int r = 0; r < 8; ++r) {
        const int j = jj + r * 16;
        const float4 w = *reinterpret_cast<const float4*>(
            W + (size_t)(row_base + j) * ldw + kofs + q * 4);
        WS[(q * 4 + 0) * 132 + j] = w.x;
        WS[(q * 4 + 1) * 132 + j] = w.y;
        WS[(q * 4 + 2) * 132 + j] = w.z;
        WS[(q * 4 + 3) * 132 + j] = w.w;
    }
}

// ---------------------------------------------------------------------------
// Packed 32-k micro-tile: acc[8 nodes][2 f32x2-pairs] += A[i0..+7][aofs..+31]*WS^T
// WS pairs are pre-packed by the LDS.128; A is warp-broadcast + splat.
// ---------------------------------------------------------------------------
__device__ __forceinline__ void mma8(ull acc[8][2], const float* WS,
                                     const float* A, int lda, int aofs,
                                     int i0, int j0) {
#pragma unroll
    for (int k4 = 0; k4 < 8; ++k4) {
        ull w[4][2];
#pragma unroll
        for (int t = 0; t < 4; ++t) {
            const ulonglong2 wv = *reinterpret_cast<const ulonglong2*>(
                WS + (k4 * 4 + t) * 132 + j0);
            w[t][0] = wv.x; w[t][1] = wv.y;
        }
#pragma unroll
        for (int u = 0; u < 8; ++u) {
            const float4 av = *reinterpret_cast<const float4*>(
                A + (size_t)(i0 + u) * lda + aofs + k4 * 4);
            ull s;
            s = splat2(av.x); fma2(acc[u][0], s, w[0][0]); fma2(acc[u][1], s, w[0][1]);
            s = splat2(av.y); fma2(acc[u][0], s, w[1][0]); fma2(acc[u][1], s, w[1][1]);
            s = splat2(av.z); fma2(acc[u][0], s, w[2][0]); fma2(acc[u][1], s, w[2][1]);
            s = splat2(av.w); fma2(acc[u][0], s, w[3][0]); fma2(acc[u][1], s, w[3][1]);
        }
    }
}

// ---------------------------------------------------------------------------
// h0 = relu(x @ W_in^T + b_in)   (128 threads, 32 nodes/block, packed)
// ---------------------------------------------------------------------------
__global__ __launch_bounds__(128) void in_gemm_kernel(const float* __restrict__ x,
                                                      const float* __restrict__ W,
                                                      const float* __restrict__ b,
                                                      float* __restrict__ hout) {
    __shared__ float X[32 * 128];
    __shared__ float WS[32 * 132];
    const int tid = threadIdx.x;
    const int node0 = blockIdx.x * 32;
    const int lane = tid & 31;
    const int i0 = (tid >> 5) * 8, j0 = lane * 4;

    for (int t = tid; t < 1024; t += 128) {
        const int i = t >> 5, c = t & 31;
        reinterpret_cast<float4*>(X + i * 128)[c] =
            reinterpret_cast<const float4*>(x + (size_t)(node0 + i) * HD)[c];
    }

    ull acc[8][2];
    {
        const ull b0 = pack2(b[j0], b[j0 + 1]);
        const ull b1 = pack2(b[j0 + 2], b[j0 + 3]);
#pragma unroll
        for (int u = 0; u < 8; ++u) { acc[u][0] = b0; acc[u][1] = b1; }
    }

    for (int kt = 0; kt < 4; ++kt) {
        __syncthreads();
        load_wtile(WS, W, 0, 128, kt * 32, tid);
        __syncthreads();
        mma8(acc, WS, X, 128, kt * 32, i0, j0);
    }

#pragma unroll
    for (int u = 0; u < 8; ++u) {
        float a0, a1, a2, a3;
        unpack2(a0, a1, acc[u][0]);
        unpack2(a2, a3, acc[u][1]);
        float4 o;
        o.x = fmaxf(a0, 0.0f); o.y = fmaxf(a1, 0.0f);
        o.z = fmaxf(a2, 0.0f); o.w = fmaxf(a3, 0.0f);
        *reinterpret_cast<float4*>(hout + (size_t)(node0 + i0 + u) * HD + j0) = o;
    }
}

// ---------------------------------------------------------------------------
// CSR build (edge structure is layer-invariant: build once per launch)
// ---------------------------------------------------------------------------
__global__ void zero_cnt_kernel() {
    const int i = blockIdx.x * 1024 + threadIdx.x;
    if (i < NN) g_cnt[i] = 0;
}
__global__ __launch_bounds__(256) void count_kernel(const int* __restrict__ ei) {
    const int e = blockIdx.x * 256 + threadIdx.x;
    atomicAdd(&g_cnt[ei[e]], 1);
}
// 1 block x 1024 threads: chunked exclusive scan of g_cnt -> g_rowptr, g_wr.
#define SCAN_CH 98   // 1024*98 = 100352 >= NN
__global__ __launch_bounds__(1024) void scan_kernel() {
    __shared__ int ps[1024];
    const int t = threadIdx.x;
    const int base = t * SCAN_CH;
    int sum = 0;
    for (int i = 0; i < SCAN_CH; ++i) {
        const int n = base + i;
        if (n < NN) sum += g_cnt[n];
    }
    ps[t] = sum;
    __syncthreads();
    for (int off = 1; off < 1024; off <<= 1) {
        int v = 0;
        if (t >= off) v = ps[t - off];
        __syncthreads();
        ps[t] += v;
        __syncthreads();
    }
    int run = (t == 0) ? 0 : ps[t - 1];  // exclusive prefix of chunk
    for (int i = 0; i < SCAN_CH; ++i) {
        const int n = base + i;
        if (n < NN) {
            g_rowptr[n] = run;
            g_wr[n] = run;
            run += g_cnt[n];
        }
    }
    if (t == 0) g_rowptr[NN] = EE;
}
__global__ __launch_bounds__(256) void scatter_kernel(const int* __restrict__ ei) {
    const int e = blockIdx.x * 256 + threadIdx.x;
    const int r = ei[e];
    const int pos = atomicAdd(&g_wr[r], 1);
    g_col[pos] = ei[EE + e];
}

// ---------------------------------------------------------------------------
// agg[n] = sum_{e in row n} |h[n] - h[col[e]]|   (warp per node, no atomics)
// ---------------------------------------------------------------------------
__global__ __launch_bounds__(256) void agg_kernel(const float* __restrict__ h,
                                                  float* __restrict__ agg) {
    const int node = blockIdx.x * 8 + (threadIdx.x >> 5);
    const int lane = threadIdx.x & 31;
    const float4 hi = *reinterpret_cast<const float4*>(h + (size_t)node * HD + lane * 4);
    float4 acc = make_float4(0.f, 0.f, 0.f, 0.f);
    int e = g_rowptr[node];
    const int eend = g_rowptr[node + 1];
    for (; e + 1 < eend; e += 2) {
        const int c0 = g_col[e];
        const int c1 = g_col[e + 1];
        const float4 a = *reinterpret_cast<const float4*>(h + (size_t)c0 * HD + lane * 4);
        const float4 b = *reinterpret_cast<const float4*>(h + (size_t)c1 * HD + lane * 4);
        acc.x += fabsf(hi.x - a.x) + fabsf(hi.x - b.x);
        acc.y += fabsf(hi.y - a.y) + fabsf(hi.y - b.y);
        acc.z += fabsf(hi.z - a.z) + fabsf(hi.z - b.z);
        acc.w += fabsf(hi.w - a.w) + fabsf(hi.w - b.w);
    }
    if (e < eend) {
        const int c0 = g_col[e];
        const float4 a = *reinterpret_cast<const float4*>(h + (size_t)c0 * HD + lane * 4);
        acc.x += fabsf(hi.x - a.x);
        acc.y += fabsf(hi.y - a.y);
        acc.z += fabsf(hi.z - a.z);
        acc.w += fabsf(hi.w - a.w);
    }
    *reinterpret_cast<float4*>(agg + (size_t)node * HD + lane * 4) = acc;
}

// ---------------------------------------------------------------------------
// Fused per-layer node kernel (128 threads, 32 nodes):
//   hw  = relu([h, agg] @ Wd^T + bd)
//   tau = softplus(hw @ Wt^T + bt)
//   block-skip GRU unless some node has tau < 0.005 (exact fallback retained)
// ---------------------------------------------------------------------------
__global__ __launch_bounds__(128) void node_kernel(
    float* __restrict__ h, const float* __restrict__ agg,
    const float* __restrict__ Wd, const float* __restrict__ bd,
    const float* __restrict__ Wt, const float* __restrict__ bt,
    const float* __restrict__ Wih, const float* __restrict__ Whh,
    const float* __restrict__ bih, const float* __restrict__ bhh,
    float* __restrict__ tau_out) {
    extern __shared__ float sm[];
    float* HA  = sm;               // [32][256]  h | agg
    float* HW  = HA + 32 * 256;    // [32][132]
    float* WS  = HW + 32 * 132;    // [32][132]
    float* GA  = WS + 32 * 132;    // [32][132]  gate r, then r*h_n
    float* GB  = GA + 32 * 132;    // [32][132]  gate z
    float* WT  = GB + 32 * 132;    // [128]
    float* TAU = WT + 128;         // [32]
    __shared__ int anyMask;

    const int tid = threadIdx.x;
    const int node0 = blockIdx.x * 32;
    const int lane = tid & 31;
    const int i0 = (tid >> 5) * 8, j0 = lane * 4;

    if (tid == 0) anyMask = 0;

    for (int t = tid; t < 2048; t += 128) {
        const int i = t >> 6, c = t & 63;
        float4 v;
        if (c < 32)
            v = reinterpret_cast<const float4*>(h + (size_t)(node0 + i) * HD)[c];
        else
            v = reinterpret_cast<const float4*>(agg + (size_t)(node0 + i) * HD)[c - 32];
        *reinterpret_cast<float4*>(HA + i * 256 + c * 4) = v;
    }
    WT[tid] = Wt[tid];

    // ---- phase 1: hw = relu([h,agg] @ Wd^T + bd) ----
    ull acc[8][2];
    {
        const ull b0 = pack2(bd[j0], bd[j0 + 1]);
        const ull b1 = pack2(bd[j0 + 2], bd[j0 + 3]);
#pragma unroll
        for (int u = 0; u < 8; ++u) { acc[u][0] = b0; acc[u][1] = b1; }
    }
    for (int kt = 0; kt < 8; ++kt) {
        __syncthreads();
        load_wtile(WS, Wd, 0, 256, kt * 32, tid);
        __syncthreads();
        mma8(acc, WS, HA, 256, kt * 32, i0, j0);
    }
#pragma unroll
    for (int u = 0; u < 8; ++u) {
        float a0, a1, a2, a3;
        unpack2(a0, a1, acc[u][0]);
        unpack2(a2, a3, acc[u][1]);
        float4 o;
        o.x = fmaxf(a0, 0.0f); o.y = fmaxf(a1, 0.0f);
        o.z = fmaxf(a2, 0.0f); o.w = fmaxf(a3, 0.0f);
        *reinterpret_cast<float4*>(HW + (i0 + u) * 132 + j0) = o;
    }
    __syncthreads();

    // ---- phase 2: tau = softplus(hw @ Wt^T + bt) ----
#pragma unroll
    for (int u = 0; u < 8; ++u) {
        const int i = i0 + u;
        float s = HW[i * 132 + lane]      * WT[lane] +
                  HW[i * 132 + lane + 32] * WT[lane + 32] +
                  HW[i * 132 + lane + 64] * WT[lane + 64] +
                  HW[i * 132 + lane + 96] * WT[lane + 96];
#pragma unroll
        for (int o = 16; o > 0; o >>= 1) s += __shfl_xor_sync(0xffffffffu, s, o);
        if (lane == 0) {
            const float tv = softplusf_(s + bt[0]);
            TAU[i] = tv;
            if (tau_out) tau_out[node0 + i] = tv;
            if (tv < 0.005f) anyMask = 1;  // benign same-value race
        }
    }
    __syncthreads();

    // ---- common case: no masked node -> h = hw, done ----
    if (anyMask == 0) {
#pragma unroll
        for (int u = 0; u < 8; ++u) {
            const float4 hw4 = *reinterpret_cast<const float4*>(HW + (i0 + u) * 132 + j0);
            *reinterpret_cast<float4*>(h + (size_t)(node0 + i0 + u) * HD + j0) = hw4;
        }
        return;
    }

    // ---- rare path: masked GRU(agg, hw). r/z gates sum gi+gh directly. ----
    // gate 0 (r) and gate 1 (z): acc = b_ih + b_hh + agg@Wih^T + hw@Whh^T
    for (int g = 0; g < 2; ++g) {
        ull ga[8][2];
        const ull b0 = pack2(bih[g * 128 + j0] + bhh[g * 128 + j0],
                             bih[g * 128 + j0 + 1] + bhh[g * 128 + j0 + 1]);
        const ull b1 = pack2(bih[g * 128 + j0 + 2] + bhh[g * 128 + j0 + 2],
                             bih[g * 128 + j0 + 3] + bhh[g * 128 + j0 + 3]);
#pragma unroll
        for (int u = 0; u < 8; ++u) { ga[u][0] = b0; ga[u][1] = b1; }
        for (int kt = 0; kt < 4; ++kt) {
            __syncthreads();
            load_wtile(WS, Wih, g * 128, 128, kt * 32, tid);
            __syncthreads();
            mma8(ga, WS, HA, 256, 128 + kt * 32, i0, j0);
        }
        for (int kt = 0; kt < 4; ++kt) {
            __syncthreads();
            load_wtile(WS, Whh, g * 128, 128, kt * 32, tid);
            __syncthreads();
            mma8(ga, WS, HW, 132, kt * 32, i0, j0);
        }
        float* G = (g == 0) ? GA : GB;
#pragma unroll
        for (int u = 0; u < 8; ++u) {
            float a0, a1, a2, a3;
            unpack2(a0, a1, ga[u][0]);
            unpack2(a2, a3, ga[u][1]);
            float4 o;
            o.x = sigmoidf_(a0); o.y = sigmoidf_(a1);
            o.z = sigmoidf_(a2); o.w = sigmoidf_(a3);
            *reinterpret_cast<float4*>(G + (i0 + u) * 132 + j0) = o;
        }
        __syncthreads();
    }

    // h_n = bhh2 + hw@Whh2^T ; GA <- r * h_n
    {
        ull hn[8][2];
        const ull b0 = pack2(bhh[256 + j0], bhh[256 + j0 + 1]);
        const ull b1 = pack2(bhh[256 + j0 + 2], bhh[256 + j0 + 3]);
#pragma unroll
        for (int u = 0; u < 8; ++u) { hn[u][0] = b0; hn[u][1] = b1; }
        for (int kt = 0; kt < 4; ++kt) {
            __syncthreads();
            load_wtile(WS, Whh, 256, 128, kt * 32, tid);
            __syncthreads();
            mma8(hn, WS, HW, 132, kt * 32, i0, j0);
        }
#pragma unroll
        for (int u = 0; u < 8; ++u) {
            float a0, a1, a2, a3;
            unpack2(a0, a1, hn[u][0]);
            unpack2(a2, a3, hn[u][1]);
            float4 r4 = *reinterpret_cast<const float4*>(GA + (i0 + u) * 132 + j0);
            float4 o;
            o.x = r4.x * a0; o.y = r4.y * a1; o.z = r4.z * a2; o.w = r4.w * a3;
            *reinterpret_cast<float4*>(GA + (i0 + u) * 132 + j0) = o;
        }
        __syncthreads();
    }

    // i_n = bih2 + agg@Wih2^T ; combine
    {
        ull in_[8][2];
        const ull b0 = pack2(bih[256 + j0], bih[256 + j0 + 1]);
        const ull b1 = pack2(bih[256 + j0 + 2], bih[256 + j0 + 3]);
#pragma unroll
        for (int u = 0; u < 8; ++u) { in_[u][0] = b0; in_[u][1] = b1; }
        for (int kt = 0; kt < 4; ++kt) {
            __syncthreads();
            load_wtile(WS, Wih, 256, 128, kt * 32, tid);
            __syncthreads();
            mma8(in_, WS, HA, 256, 128 + kt * 32, i0, j0);
        }
#pragma unroll
        for (int u = 0; u < 8; ++u) {
            float a0, a1, a2, a3;
            unpack2(a0, a1, in_[u][0]);
            unpack2(a2, a3, in_[u][1]);
            const float iv[4] = {a0, a1, a2, a3};
            const float4 rh4 = *reinterpret_cast<const float4*>(GA + (i0 + u) * 132 + j0);
            const float4 z4  = *reinterpret_cast<const float4*>(GB + (i0 + u) * 132 + j0);
            const float4 hw4 = *reinterpret_cast<const float4*>(HW + (i0 + u) * 132 + j0);
            const float rhv[4] = {rh4.x, rh4.y, rh4.z, rh4.w};
            const float zv[4]  = {z4.x, z4.y, z4.z, z4.w};
            const float hwv[4] = {hw4.x, hw4.y, hw4.z, hw4.w};
            const bool msk = TAU[i0 + u] < 0.005f;
            float ov[4];
#pragma unroll
            for (int v = 0; v < 4; ++v) {
                const float n = tanhf(iv[v] + rhv[v]);
                const float hn = (1.0f - zv[v]) * n + zv[v] * hwv[v];
                ov[v] = msk ? hn : hwv[v];
            }
            *reinterpret_cast<float4*>(h + (size_t)(node0 + i0 + u) * HD + j0) =
                make_float4(ov[0], ov[1], ov[2], ov[3]);
        }
    }
}

// ---------------------------------------------------------------------------
// out = h @ Wo^T + bo   (warp per node)
// ---------------------------------------------------------------------------
__global__ __launch_bounds__(256) void out_kernel(const float* __restrict__ h,
                                                  const float* __restrict__ Wo,
                                                  const float* __restrict__ bo,
                                                  float* __restrict__ out) {
    const int nid = blockIdx.x * 8 + (threadIdx.x >> 5);
    const int lane = threadIdx.x & 31;
    float a0 = 0.f, a1 = 0.f;
#pragma unroll
    for (int t = 0; t < 4; ++t) {
        const float hv = h[(size_t)nid * HD + lane + t * 32];
        a0 = fmaf(hv, Wo[lane + t * 32], a0);
        a1 = fmaf(hv, Wo[HD + lane + t * 32], a1);
    }
#pragma unroll
    for (int o = 16; o > 0; o >>= 1) {
        a0 += __shfl_xor_sync(0xffffffffu, a0, o);
        a1 += __shfl_xor_sync(0xffffffffu, a1, o);
    }
    if (lane == 0) {
        out[(size_t)nid * 2 + 0] = a0 + bo[0];
        out[(size_t)nid * 2 + 1] = a1 + bo[1];
    }
}

// ---------------------------------------------------------------------------
extern "C" void kernel_launch(void* const* d_in, const int* in_sizes, int n_in,
                              void* d_out, int out_size) {
    const float* x    = (const float*)d_in[0];
    const int*   ei   = (const int*)d_in[1];   // int32 (JAX x64-disabled)
    const float* W_in = (const float*)d_in[2];
    const float* b_in = (const float*)d_in[3];
    const float* Wd   = (const float*)d_in[4];
    const float* bd   = (const float*)d_in[5];
    const float* Wt   = (const float*)d_in[6];
    const float* bt   = (const float*)d_in[7];
    const float* Wih  = (const float*)d_in[8];
    const float* Whh  = (const float*)d_in[9];
    const float* bih  = (const float*)d_in[10];
    const float* bhh  = (const float*)d_in[11];
    const float* Wo   = (const float*)d_in[12];
    const float* bo   = (const float*)d_in[13];

    float* out = (float*)d_out;
    float* tau_out = (out_size >= NN * 3) ? out + (size_t)NN * 2 : nullptr;

    float *h, *agg;
    cudaGetSymbolAddress((void**)&h, g_h);
    cudaGetSymbolAddress((void**)&agg, g_agg);

    const size_t smem_node =
        (32 * 256 + 32 * 132 * 4 + 128 + 32) * sizeof(float);  // ~101 KB
    cudaFuncSetAttribute(node_kernel, cudaFuncAttributeMaxDynamicSharedMemorySize,
                         (int)smem_node);

    // CSR build (edge structure is the same for both layers)
    zero_cnt_kernel<<<(NN + 1023) / 1024, 1024>>>();
    count_kernel<<<EE / 256, 256>>>(ei);
    scan_kernel<<<1, 1024>>>();
    scatter_kernel<<<EE / 256, 256>>>(ei);

    in_gemm_kernel<<<NN / 32, 128>>>(x, W_in, b_in, h);

    for (int l = 0; l < 2; ++l) {
        agg_kernel<<<NN / 8, 256>>>(h, agg);
        node_kernel<<<NN / 32, 128, smem_node>>>(
            h, agg, Wd + (size_t)l * HD * 2 * HD, bd + (size_t)l * HD,
            Wt, bt, Wih, Whh, bih, bhh, (l == 1) ? tau_out : nullptr);
    }

    out_kernel<<<NN / 8, 256>>>(h, Wo, bo, out);
}

// round 5
// speedup vs baseline: 2.4468x; 1.1250x over previous
#include <cuda_runtime.h>
#include <cstdint>
#include <cstddef>

#define NN 100000
#define EE 1600000
#define HD 128

typedef unsigned long long ull;

// Scratch (__device__ globals; allocations forbidden)
__device__ float g_h[(size_t)NN * HD];
__device__ float g_agg[(size_t)NN * HD];
__device__ int   g_cnt[NN];
__device__ int   g_rowptr[NN + 1];
__device__ int   g_wr[NN];
__device__ int   g_col[EE];

__device__ __forceinline__ float sigmoidf_(float x) { return 1.0f / (1.0f + expf(-x)); }
__device__ __forceinline__ float softplusf_(float x) {
    return fmaxf(x, 0.0f) + log1pf(expf(-fabsf(x)));
}

// ---- packed f32x2 helpers (FFMA2 only reachable via PTX) ----
__device__ __forceinline__ ull splat2(float x) {
    ull r; asm("mov.b64 %0, {%1, %1};" : "=l"(r) : "f"(x)); return r;
}
__device__ __forceinline__ ull pack2(float lo, float hi) {
    ull r; asm("mov.b64 %0, {%1, %2};" : "=l"(r) : "f"(lo), "f"(hi)); return r;
}
__device__ __forceinline__ void unpack2(float& lo, float& hi, ull v) {
    asm("mov.b64 {%0, %1}, %2;" : "=f"(lo), "=f"(hi) : "l"(v));
}
__device__ __forceinline__ void fma2(ull& d, ull a, ull b) {
    asm("fma.rn.f32x2 %0, %1, %2, %3;" : "=l"(d) : "l"(a), "l"(b), "l"(d));
}

// ---------------------------------------------------------------------------
// Weight tile loader (128 threads): rows [row_base,+128) x cols [kofs,+32)
// of row-major W (ld=ldw) into WS k-major: WS[k*132 + j].
// ---------------------------------------------------------------------------
__device__ __forceinline__ void load_wtile(float* WS, const float* __restrict__ W,
                                           int row_base, int ldw, int kofs, int tid) {
    const int q  = tid & 7;
    const int jj = tid >> 3;
#pragma unroll
    for (int r = 0; r < 8; ++r) {
        const int j = jj + r * 16;
        const float4 w = *reinterpret_cast<const float4*>(
            W + (size_t)(row_base + j) * ldw + kofs + q * 4);
        WS[(q * 4 + 0) * 132 + j] = w.x;
        WS[(q * 4 + 1) * 132 + j] = w.y;
        WS[(q * 4 + 2) * 132 + j] = w.z;
        WS[(q * 4 + 3) * 132 + j] = w.w;
    }
}

// ---------------------------------------------------------------------------
// Packed 32-k micro-tile: acc[8 nodes][2 pairs] += A[i0..+7][aofs..+31]*WS^T
// ---------------------------------------------------------------------------
__device__ __forceinline__ void mma8(ull acc[8][2], const float* WS,
                                     const float* A, int lda, int aofs,
                                     int i0, int j0) {
#pragma unroll
    for (int k4 = 0; k4 < 8; ++k4) {
        ull w[4][2];
#pragma unroll
        for (int t = 0; t < 4; ++t) {
            const ulonglong2 wv = *reinterpret_cast<const ulonglong2*>(
                WS + (k4 * 4 + t) * 132 + j0);
            w[t][0] = wv.x; w[t][1] = wv.y;
        }
#pragma unroll
        for (int u = 0; u < 8; ++u) {
            const float4 av = *reinterpret_cast<const float4*>(
                A + (size_t)(i0 + u) * lda + aofs + k4 * 4);
            ull s;
            s = splat2(av.x); fma2(acc[u][0], s, w[0][0]); fma2(acc[u][1], s, w[0][1]);
            s = splat2(av.y); fma2(acc[u][0], s, w[1][0]); fma2(acc[u][1], s, w[1][1]);
            s = splat2(av.z); fma2(acc[u][0], s, w[2][0]); fma2(acc[u][1], s, w[2][1]);
            s = splat2(av.w); fma2(acc[u][0], s, w[3][0]); fma2(acc[u][1], s, w[3][1]);
        }
    }
}

// ---------------------------------------------------------------------------
// h0 = relu(x @ W_in^T + b_in)
// ---------------------------------------------------------------------------
__global__ __launch_bounds__(128) void in_gemm_kernel(const float* __restrict__ x,
                                                      const float* __restrict__ W,
                                                      const float* __restrict__ b,
                                                      float* __restrict__ hout) {
    __shared__ float X[32 * 128];
    __shared__ float WS[32 * 132];
    const int tid = threadIdx.x;
    const int node0 = blockIdx.x * 32;
    const int lane = tid & 31;
    const int i0 = (tid >> 5) * 8, j0 = lane * 4;

    for (int t = tid; t < 1024; t += 128) {
        const int i = t >> 5, c = t & 31;
        reinterpret_cast<float4*>(X + i * 128)[c] =
            reinterpret_cast<const float4*>(x + (size_t)(node0 + i) * HD)[c];
    }

    ull acc[8][2];
    {
        const ull b0 = pack2(b[j0], b[j0 + 1]);
        const ull b1 = pack2(b[j0 + 2], b[j0 + 3]);
#pragma unroll
        for (int u = 0; u < 8; ++u) { acc[u][0] = b0; acc[u][1] = b1; }
    }

    for (int kt = 0; kt < 4; ++kt) {
        __syncthreads();
        load_wtile(WS, W, 0, 128, kt * 32, tid);
        __syncthreads();
        mma8(acc, WS, X, 128, kt * 32, i0, j0);
    }

#pragma unroll
    for (int u = 0; u < 8; ++u) {
        float a0, a1, a2, a3;
        unpack2(a0, a1, acc[u][0]);
        unpack2(a2, a3, acc[u][1]);
        float4 o;
        o.x = fmaxf(a0, 0.0f); o.y = fmaxf(a1, 0.0f);
        o.z = fmaxf(a2, 0.0f); o.w = fmaxf(a3, 0.0f);
        *reinterpret_cast<float4*>(hout + (size_t)(node0 + i0 + u) * HD + j0) = o;
    }
}

// ---------------------------------------------------------------------------
// CSR build (edge structure is layer-invariant: build once per launch)
// ---------------------------------------------------------------------------
__global__ void zero_cnt_kernel() {
    const int i = blockIdx.x * 1024 + threadIdx.x;
    if (i < NN) g_cnt[i] = 0;
}
__global__ __launch_bounds__(256) void count_kernel(const int* __restrict__ ei) {
    const int idx = blockIdx.x * 256 + threadIdx.x;  // 2 edges per thread
    const int2 r = reinterpret_cast<const int2*>(ei)[idx];
    atomicAdd(&g_cnt[r.x], 1);
    atomicAdd(&g_cnt[r.y], 1);
}
#define SCAN_CH 98   // 1024*98 >= NN
__global__ __launch_bounds__(1024) void scan_kernel() {
    __shared__ int ps[1024];
    const int t = threadIdx.x;
    const int base = t * SCAN_CH;
    int sum = 0;
    for (int i = 0; i < SCAN_CH; ++i) {
        const int n = base + i;
        if (n < NN) sum += g_cnt[n];
    }
    ps[t] = sum;
    __syncthreads();
    for (int off = 1; off < 1024; off <<= 1) {
        int v = 0;
        if (t >= off) v = ps[t - off];
        __syncthreads();
        ps[t] += v;
        __syncthreads();
    }
    int run = (t == 0) ? 0 : ps[t - 1];
    for (int i = 0; i < SCAN_CH; ++i) {
        const int n = base + i;
        if (n < NN) {
            g_rowptr[n] = run;
            g_wr[n] = run;
            run += g_cnt[n];
        }
    }
    if (t == 0) g_rowptr[NN] = EE;
}
__global__ __launch_bounds__(256) void scatter_kernel(const int* __restrict__ ei) {
    const int idx = blockIdx.x * 256 + threadIdx.x;  // 2 edges per thread
    const int2 r = reinterpret_cast<const int2*>(ei)[idx];
    const int2 c = reinterpret_cast<const int2*>(ei + EE)[idx];
    int pos = atomicAdd(&g_wr[r.x], 1);
    g_col[pos] = c.x;
    pos = atomicAdd(&g_wr[r.y], 1);
    g_col[pos] = c.y;
}

// ---------------------------------------------------------------------------
// agg[n] = sum_{e in row n} |h[n] - h[col[e]]|  (warp/node, gather, MLP=4)
// ---------------------------------------------------------------------------
__global__ __launch_bounds__(512) void agg_kernel(const float* __restrict__ h,
                                                  float* __restrict__ agg) {
    const int node = blockIdx.x * 16 + (threadIdx.x >> 5);
    const int lane = threadIdx.x & 31;
    const float4 hi = *reinterpret_cast<const float4*>(h + (size_t)node * HD + lane * 4);
    float4 acc = make_float4(0.f, 0.f, 0.f, 0.f);
    int e = g_rowptr[node];
    const int eend = g_rowptr[node + 1];
    for (; e + 3 < eend; e += 4) {
        const int c0 = g_col[e], c1 = g_col[e + 1];
        const int c2 = g_col[e + 2], c3 = g_col[e + 3];
        const float4 a = *reinterpret_cast<const float4*>(h + (size_t)c0 * HD + lane * 4);
        const float4 b = *reinterpret_cast<const float4*>(h + (size_t)c1 * HD + lane * 4);
        const float4 c = *reinterpret_cast<const float4*>(h + (size_t)c2 * HD + lane * 4);
        const float4 d = *reinterpret_cast<const float4*>(h + (size_t)c3 * HD + lane * 4);
        acc.x += fabsf(hi.x - a.x) + fabsf(hi.x - b.x) + fabsf(hi.x - c.x) + fabsf(hi.x - d.x);
        acc.y += fabsf(hi.y - a.y) + fabsf(hi.y - b.y) + fabsf(hi.y - c.y) + fabsf(hi.y - d.y);
        acc.z += fabsf(hi.z - a.z) + fabsf(hi.z - b.z) + fabsf(hi.z - c.z) + fabsf(hi.z - d.z);
        acc.w += fabsf(hi.w - a.w) + fabsf(hi.w - b.w) + fabsf(hi.w - c.w) + fabsf(hi.w - d.w);
    }
    for (; e < eend; ++e) {
        const int c0 = g_col[e];
        const float4 a = *reinterpret_cast<const float4*>(h + (size_t)c0 * HD + lane * 4);
        acc.x += fabsf(hi.x - a.x);
        acc.y += fabsf(hi.y - a.y);
        acc.z += fabsf(hi.z - a.z);
        acc.w += fabsf(hi.w - a.w);
    }
    *reinterpret_cast<float4*>(agg + (size_t)node * HD + lane * 4) = acc;
}

// ---------------------------------------------------------------------------
// Fused per-layer node kernel (128 threads, 32 nodes, 3 blocks/SM):
//   hw  = relu([h, agg] @ Wd^T + bd)
//   tau = softplus(hw @ Wt^T + bt)
//   block-skip GRU unless some node has tau < 0.005 (exact fallback retained;
//   gates live in the dead h-half of HA — no extra smem)
//   if out != null (last layer): fused out = h@Wo^T + bo, h not stored
// ---------------------------------------------------------------------------
__global__ __launch_bounds__(128, 3) void node_kernel(
    float* __restrict__ h, const float* __restrict__ agg,
    const float* __restrict__ Wd, const float* __restrict__ bd,
    const float* __restrict__ Wt, const float* __restrict__ bt,
    const float* __restrict__ Wih, const float* __restrict__ Whh,
    const float* __restrict__ bih, const float* __restrict__ bhh,
    const float* __restrict__ Wo, const float* __restrict__ bo,
    float* __restrict__ out, float* __restrict__ tau_out) {
    extern __shared__ float sm[];
    float* HA  = sm;               // [32][256]  h | agg  (h half is dead after phase 1)
    float* HW  = HA + 32 * 256;    // [32][132]
    float* WS  = HW + 32 * 132;    // [32][132]
    float* WT  = WS + 32 * 132;    // [128]
    float* WoS = WT + 128;         // [256]
    float* TAU = WoS + 256;        // [32]
    __shared__ int anyMask;

    const int tid = threadIdx.x;
    const int node0 = blockIdx.x * 32;
    const int lane = tid & 31;
    const int i0 = (tid >> 5) * 8, j0 = lane * 4;

    if (tid == 0) anyMask = 0;

    for (int t = tid; t < 2048; t += 128) {
        const int i = t >> 6, c = t & 63;
        float4 v;
        if (c < 32)
            v = reinterpret_cast<const float4*>(h + (size_t)(node0 + i) * HD)[c];
        else
            v = reinterpret_cast<const float4*>(agg + (size_t)(node0 + i) * HD)[c - 32];
        *reinterpret_cast<float4*>(HA + i * 256 + c * 4) = v;
    }
    WT[tid] = Wt[tid];
    if (out) { WoS[tid] = Wo[tid]; WoS[tid + 128] = Wo[tid + 128]; }

    // ---- phase 1: hw = relu([h,agg] @ Wd^T + bd) ----
    ull acc[8][2];
    {
        const ull b0 = pack2(bd[j0], bd[j0 + 1]);
        const ull b1 = pack2(bd[j0 + 2], bd[j0 + 3]);
#pragma unroll
        for (int u = 0; u < 8; ++u) { acc[u][0] = b0; acc[u][1] = b1; }
    }
    for (int kt = 0; kt < 8; ++kt) {
        __syncthreads();
        load_wtile(WS, Wd, 0, 256, kt * 32, tid);
        __syncthreads();
        mma8(acc, WS, HA, 256, kt * 32, i0, j0);
    }
#pragma unroll
    for (int u = 0; u < 8; ++u) {
        float a0, a1, a2, a3;
        unpack2(a0, a1, acc[u][0]);
        unpack2(a2, a3, acc[u][1]);
        float4 o;
        o.x = fmaxf(a0, 0.0f); o.y = fmaxf(a1, 0.0f);
        o.z = fmaxf(a2, 0.0f); o.w = fmaxf(a3, 0.0f);
        *reinterpret_cast<float4*>(HW + (i0 + u) * 132 + j0) = o;
    }
    __syncthreads();

    // ---- phase 2: tau = softplus(hw @ Wt^T + bt) ----
#pragma unroll
    for (int u = 0; u < 8; ++u) {
        const int i = i0 + u;
        float s = HW[i * 132 + lane]      * WT[lane] +
                  HW[i * 132 + lane + 32] * WT[lane + 32] +
                  HW[i * 132 + lane + 64] * WT[lane + 64] +
                  HW[i * 132 + lane + 96] * WT[lane + 96];
#pragma unroll
        for (int o = 16; o > 0; o >>= 1) s += __shfl_xor_sync(0xffffffffu, s, o);
        if (lane == 0) {
            const float tv = softplusf_(s + bt[0]);
            TAU[i] = tv;
            if (tau_out) tau_out[node0 + i] = tv;
            if (tv < 0.005f) anyMask = 1;  // benign same-value race
        }
    }
    __syncthreads();

    // ---- common case: no masked node -> h_new = hw ----
    if (anyMask == 0) {
        const float bo0 = out ? bo[0] : 0.f, bo1 = out ? bo[1] : 0.f;
#pragma unroll
        for (int u = 0; u < 8; ++u) {
            const float4 hw4 = *reinterpret_cast<const float4*>(HW + (i0 + u) * 132 + j0);
            if (out) {
                float p0 = hw4.x * WoS[j0]       + hw4.y * WoS[j0 + 1] +
                           hw4.z * WoS[j0 + 2]   + hw4.w * WoS[j0 + 3];
                float p1 = hw4.x * WoS[128 + j0]     + hw4.y * WoS[128 + j0 + 1] +
                           hw4.z * WoS[128 + j0 + 2] + hw4.w * WoS[128 + j0 + 3];
#pragma unroll
                for (int o = 16; o > 0; o >>= 1) {
                    p0 += __shfl_xor_sync(0xffffffffu, p0, o);
                    p1 += __shfl_xor_sync(0xffffffffu, p1, o);
                }
                if (lane == 0) {
                    *reinterpret_cast<float2*>(out + (size_t)(node0 + i0 + u) * 2) =
                        make_float2(p0 + bo0, p1 + bo1);
                }
            } else {
                *reinterpret_cast<float4*>(h + (size_t)(node0 + i0 + u) * HD + j0) = hw4;
            }
        }
        return;
    }

    // ---- rare path: exact masked GRU(agg, hw) ----
    // Gates are stored in the dead h-half of HA (same-thread read-back).
    // 1) r = sigmoid(b_ihr + b_hhr + agg@Wihr^T + hw@Whhr^T)
    {
        ull ga[8][2];
        const ull b0 = pack2(bih[j0] + bhh[j0], bih[j0 + 1] + bhh[j0 + 1]);
        const ull b1 = pack2(bih[j0 + 2] + bhh[j0 + 2], bih[j0 + 3] + bhh[j0 + 3]);
#pragma unroll
        for (int u = 0; u < 8; ++u) { ga[u][0] = b0; ga[u][1] = b1; }
        for (int kt = 0; kt < 4; ++kt) {
            __syncthreads();
            load_wtile(WS, Wih, 0, 128, kt * 32, tid);
            __syncthreads();
            mma8(ga, WS, HA, 256, 128 + kt * 32, i0, j0);
        }
        for (int kt = 0; kt < 4; ++kt) {
            __syncthreads();
            load_wtile(WS, Whh, 0, 128, kt * 32, tid);
            __syncthreads();
            mma8(ga, WS, HW, 132, kt * 32, i0, j0);
        }
#pragma unroll
        for (int u = 0; u < 8; ++u) {
            float a0, a1, a2, a3;
            unpack2(a0, a1, ga[u][0]);
            unpack2(a2, a3, ga[u][1]);
            *reinterpret_cast<float4*>(HA + (i0 + u) * 256 + j0) =
                make_float4(sigmoidf_(a0), sigmoidf_(a1), sigmoidf_(a2), sigmoidf_(a3));
        }
    }
    // 2) h_n = b_hhn + hw@Whhn^T ;  HA <- r * h_n
    {
        ull hn[8][2];
        const ull b0 = pack2(bhh[256 + j0], bhh[256 + j0 + 1]);
        const ull b1 = pack2(bhh[256 + j0 + 2], bhh[256 + j0 + 3]);
#pragma unroll
        for (int u = 0; u < 8; ++u) { hn[u][0] = b0; hn[u][1] = b1; }
        for (int kt = 0; kt < 4; ++kt) {
            __syncthreads();
            load_wtile(WS, Whh, 256, 128, kt * 32, tid);
            __syncthreads();
            mma8(hn, WS, HW, 132, kt * 32, i0, j0);
        }
#pragma unroll
        for (int u = 0; u < 8; ++u) {
            float a0, a1, a2, a3;
            unpack2(a0, a1, hn[u][0]);
            unpack2(a2, a3, hn[u][1]);
            float4 r4 = *reinterpret_cast<const float4*>(HA + (i0 + u) * 256 + j0);
            *reinterpret_cast<float4*>(HA + (i0 + u) * 256 + j0) =
                make_float4(r4.x * a0, r4.y * a1, r4.z * a2, r4.w * a3);
        }
    }
    // 3) n = tanh(b_ihn + agg@Wihn^T + r*h_n) -> HA
    {
        ull in_[8][2];
        const ull b0 = pack2(bih[256 + j0], bih[256 + j0 + 1]);
        const ull b1 = pack2(bih[256 + j0 + 2], bih[256 + j0 + 3]);
#pragma unroll
        for (int u = 0; u < 8; ++u) { in_[u][0] = b0; in_[u][1] = b1; }
        for (int kt = 0; kt < 4; ++kt) {
            __syncthreads();
            load_wtile(WS, Wih, 256, 128, kt * 32, tid);
            __syncthreads();
            mma8(in_, WS, HA, 256, 128 + kt * 32, i0, j0);
        }
#pragma unroll
        for (int u = 0; u < 8; ++u) {
            float a0, a1, a2, a3;
            unpack2(a0, a1, in_[u][0]);
            unpack2(a2, a3, in_[u][1]);
            float4 rh4 = *reinterpret_cast<const float4*>(HA + (i0 + u) * 256 + j0);
            *reinterpret_cast<float4*>(HA + (i0 + u) * 256 + j0) =
                make_float4(tanhf(a0 + rh4.x), tanhf(a1 + rh4.y),
                            tanhf(a2 + rh4.z), tanhf(a3 + rh4.w));
        }
    }
    // 4) z = sigmoid(b_ihz + b_hhz + agg@Wihz^T + hw@Whhz^T); combine + output
    {
        ull gz[8][2];
        const ull b0 = pack2(bih[128 + j0] + bhh[128 + j0],
                             bih[128 + j0 + 1] + bhh[128 + j0 + 1]);
        const ull b1 = pack2(bih[128 + j0 + 2] + bhh[128 + j0 + 2],
                             bih[128 + j0 + 3] + bhh[128 + j0 + 3]);
#pragma unroll
        for (int u = 0; u < 8; ++u) { gz[u][0] = b0; gz[u][1] = b1; }
        for (int kt = 0; kt < 4; ++kt) {
            __syncthreads();
            load_wtile(WS, Wih, 128, 128, kt * 32, tid);
            __syncthreads();
            mma8(gz, WS, HA, 256, 128 + kt * 32, i0, j0);
        }
        for (int kt = 0; kt < 4; ++kt) {
            __syncthreads();
            load_wtile(WS, Whh, 128, 128, kt * 32, tid);
            __syncthreads();
            mma8(gz, WS, HW, 132, kt * 32, i0, j0);
        }
        const float bo0 = out ? bo[0] : 0.f, bo1 = out ? bo[1] : 0.f;
#pragma unroll
        for (int u = 0; u < 8; ++u) {
            float a0, a1, a2, a3;
            unpack2(a0, a1, gz[u][0]);
            unpack2(a2, a3, gz[u][1]);
            const float zv[4] = {sigmoidf_(a0), sigmoidf_(a1), sigmoidf_(a2), sigmoidf_(a3)};
            const float4 n4  = *reinterpret_cast<const float4*>(HA + (i0 + u) * 256 + j0);
            const float4 hw4 = *reinterpret_cast<const float4*>(HW + (i0 + u) * 132 + j0);
            const float nv[4]  = {n4.x, n4.y, n4.z, n4.w};
            const float hwv[4] = {hw4.x, hw4.y, hw4.z, hw4.w};
            const bool msk = TAU[i0 + u] < 0.005f;
            float ov[4];
#pragma unroll
            for (int v = 0; v < 4; ++v) {
                const float hn = (1.0f - zv[v]) * nv[v] + zv[v] * hwv[v];
                ov[v] = msk ? hn : hwv[v];
            }
            if (out) {
                float p0 = ov[0] * WoS[j0]       + ov[1] * WoS[j0 + 1] +
                           ov[2] * WoS[j0 + 2]   + ov[3] * WoS[j0 + 3];
                float p1 = ov[0] * WoS[128 + j0]     + ov[1] * WoS[128 + j0 + 1] +
                           ov[2] * WoS[128 + j0 + 2] + ov[3] * WoS[128 + j0 + 3];
#pragma unroll
                for (int o = 16; o > 0; o >>= 1) {
                    p0 += __shfl_xor_sync(0xffffffffu, p0, o);
                    p1 += __shfl_xor_sync(0xffffffffu, p1, o);
                }
                if (lane == 0) {
                    *reinterpret_cast<float2*>(out + (size_t)(node0 + i0 + u) * 2) =
                        make_float2(p0 + bo0, p1 + bo1);
                }
            } else {
                *reinterpret_cast<float4*>(h + (size_t)(node0 + i0 + u) * HD + j0) =
                    make_float4(ov[0], ov[1], ov[2], ov[3]);
            }
        }
    }
}

// ---------------------------------------------------------------------------
extern "C" void kernel_launch(void* const* d_in, const int* in_sizes, int n_in,
                              void* d_out, int out_size) {
    const float* x    = (const float*)d_in[0];
    const int*   ei   = (const int*)d_in[1];   // int32 (JAX x64-disabled)
    const float* W_in = (const float*)d_in[2];
    const float* b_in = (const float*)d_in[3];
    const float* Wd   = (const float*)d_in[4];
    const float* bd   = (const float*)d_in[5];
    const float* Wt   = (const float*)d_in[6];
    const float* bt   = (const float*)d_in[7];
    const float* Wih  = (const float*)d_in[8];
    const float* Whh  = (const float*)d_in[9];
    const float* bih  = (const float*)d_in[10];
    const float* bhh  = (const float*)d_in[11];
    const float* Wo   = (const float*)d_in[12];
    const float* bo   = (const float*)d_in[13];

    float* out = (float*)d_out;
    float* tau_out = (out_size >= NN * 3) ? out + (size_t)NN * 2 : nullptr;

    float *h, *agg;
    cudaGetSymbolAddress((void**)&h, g_h);
    cudaGetSymbolAddress((void**)&agg, g_agg);

    const size_t smem_node =
        (32 * 256 + 32 * 132 * 2 + 128 + 256 + 32) * sizeof(float);  // ~68 KB
    cudaFuncSetAttribute(node_kernel, cudaFuncAttributeMaxDynamicSharedMemorySize,
                         (int)smem_node);

    // CSR build (same structure for both layers)
    zero_cnt_kernel<<<(NN + 1023) / 1024, 1024>>>();
    count_kernel<<<EE / 512, 256>>>(ei);
    scan_kernel<<<1, 1024>>>();
    scatter_kernel<<<EE / 512, 256>>>(ei);

    in_gemm_kernel<<<NN / 32, 128>>>(x, W_in, b_in, h);

    for (int l = 0; l < 2; ++l) {
        agg_kernel<<<NN / 16, 512>>>(h, agg);
        node_kernel<<<NN / 32, 128, smem_node>>>(
            h, agg, Wd + (size_t)l * HD * 2 * HD, bd + (size_t)l * HD,
            Wt, bt, Wih, Whh, bih, bhh, Wo, bo,
            (l == 1) ? out : nullptr, (l == 1) ? tau_out : nullptr);
    }
}

// round 6
// speedup vs baseline: 3.2625x; 1.3334x over previous
#include <cuda_runtime.h>
#include <cstdint>
#include <cstddef>

#define NN 100000
#define EE 1600000
#define HD 128
#define CAP 64

typedef unsigned long long ull;

// ---- scratch (__device__ globals; allocations forbidden) ----
__device__ float g_h[(size_t)NN * HD];
__device__ float g_agg[(size_t)NN * HD];
__device__ float g_hw[(size_t)NN * HD];          // rare-path GEMM operand
__device__ int   g_cnt[NN];
__device__ int   g_col[(size_t)NN * CAP];
__device__ int   g_spill_cnt;
__device__ int2  g_spill[EE];
// k-major transposed weights (built once per launch)
__device__ __align__(16) float g_WinT[128 * 128];
__device__ __align__(16) float g_WdT[2 * 256 * 128];
__device__ __align__(16) float g_WihT[3 * 128 * 128];
__device__ __align__(16) float g_WhhT[3 * 128 * 128];

__device__ __forceinline__ float sigmoidf_(float x) { return 1.0f / (1.0f + expf(-x)); }
__device__ __forceinline__ float softplusf_(float x) {
    return fmaxf(x, 0.0f) + log1pf(expf(-fabsf(x)));
}

// ---- packed f32x2 helpers (FFMA2 only reachable via PTX) ----
__device__ __forceinline__ ull splat2(float x) {
    ull r; asm("mov.b64 %0, {%1, %1};" : "=l"(r) : "f"(x)); return r;
}
__device__ __forceinline__ ull pack2(float lo, float hi) {
    ull r; asm("mov.b64 %0, {%1, %2};" : "=l"(r) : "f"(lo), "f"(hi)); return r;
}
__device__ __forceinline__ void unpack2(float& lo, float& hi, ull v) {
    asm("mov.b64 {%0, %1}, %2;" : "=f"(lo), "=f"(hi) : "l"(v));
}
__device__ __forceinline__ void fma2(ull& d, ull a, ull b) {
    asm("fma.rn.f32x2 %0, %1, %2, %3;" : "=l"(d) : "l"(a), "l"(b), "l"(d));
}

// ---------------------------------------------------------------------------
// Packed 32-k micro-tile, k-major weights straight from global:
//   acc[8 nodes][2 f32x2 pairs] += A[i0..+7][aofs..+31] * WT(k-major, ld=128)
// WT rows: 512B coalesced LDG.128 per warp; A rows: warp-broadcast LDG.128.
// ---------------------------------------------------------------------------
__device__ __forceinline__ void mma8g(ull acc[8][2], const float* __restrict__ WT,
                                      const float* __restrict__ A, int lda, int aofs,
                                      int i0, int j0) {
#pragma unroll
    for (int k4 = 0; k4 < 8; ++k4) {
        ull w[4][2];
#pragma unroll
        for (int t = 0; t < 4; ++t) {
            const ulonglong2 wv = *reinterpret_cast<const ulonglong2*>(
                WT + (k4 * 4 + t) * 128 + j0);
            w[t][0] = wv.x; w[t][1] = wv.y;
        }
#pragma unroll
        for (int u = 0; u < 8; ++u) {
            const float4 av = *reinterpret_cast<const float4*>(
                A + (size_t)(i0 + u) * lda + aofs + k4 * 4);
            ull s;
            s = splat2(av.x); fma2(acc[u][0], s, w[0][0]); fma2(acc[u][1], s, w[0][1]);
            s = splat2(av.y); fma2(acc[u][0], s, w[1][0]); fma2(acc[u][1], s, w[1][1]);
            s = splat2(av.z); fma2(acc[u][0], s, w[2][0]); fma2(acc[u][1], s, w[2][1]);
            s = splat2(av.w); fma2(acc[u][0], s, w[3][0]); fma2(acc[u][1], s, w[3][1]);
        }
    }
}

// ---------------------------------------------------------------------------
// One-time weight transposes (row-major [j][k] -> k-major [k][j])
// ---------------------------------------------------------------------------
__global__ void t_win_kernel(const float* __restrict__ W) {
    const int e = blockIdx.x * 256 + threadIdx.x;        // 16384
    const int j = e >> 7, k = e & 127;
    g_WinT[k * 128 + j] = W[e];
}
__global__ void t_wd_kernel(const float* __restrict__ W) {
    const int e = blockIdx.x * 256 + threadIdx.x;        // 65536
    const int l = e >> 15, rem = e & 32767;
    const int j = rem >> 8, k = rem & 255;
    g_WdT[l * 32768 + k * 128 + j] = W[e];
}
__global__ void t_wih_kernel(const float* __restrict__ W) {
    const int e = blockIdx.x * 256 + threadIdx.x;        // 49152
    const int j = e >> 7, k = e & 127;
    const int g = j >> 7, jj = j & 127;
    g_WihT[g * 16384 + k * 128 + jj] = W[e];
}
__global__ void t_whh_kernel(const float* __restrict__ W) {
    const int e = blockIdx.x * 256 + threadIdx.x;        // 49152
    const int j = e >> 7, k = e & 127;
    const int g = j >> 7, jj = j & 127;
    g_WhhT[g * 16384 + k * 128 + jj] = W[e];
}

// ---------------------------------------------------------------------------
// h0 = relu(x @ W_in^T + b_in)  — no smem, no syncs
// ---------------------------------------------------------------------------
__global__ __launch_bounds__(128, 4) void in_gemm_kernel(const float* __restrict__ x,
                                                         const float* __restrict__ b) {
    const int node0 = blockIdx.x * 32;
    const int lane = threadIdx.x & 31;
    const int i0 = (threadIdx.x >> 5) * 8, j0 = lane * 4;
    const float* A = x + (size_t)node0 * HD;

    ull acc[8][2];
    {
        const float4 b4 = *reinterpret_cast<const float4*>(b + j0);
        const ull b0 = pack2(b4.x, b4.y), b1 = pack2(b4.z, b4.w);
#pragma unroll
        for (int u = 0; u < 8; ++u) { acc[u][0] = b0; acc[u][1] = b1; }
    }
#pragma unroll 1
    for (int kt = 0; kt < 4; ++kt)
        mma8g(acc, g_WinT + kt * 4096, A, HD, kt * 32, i0, j0);

#pragma unroll
    for (int u = 0; u < 8; ++u) {
        float a0, a1, a2, a3;
        unpack2(a0, a1, acc[u][0]);
        unpack2(a2, a3, acc[u][1]);
        *reinterpret_cast<float4*>(g_h + (size_t)(node0 + i0 + u) * HD + j0) =
            make_float4(fmaxf(a0, 0.f), fmaxf(a1, 0.f), fmaxf(a2, 0.f), fmaxf(a3, 0.f));
    }
}

// ---------------------------------------------------------------------------
// Edge structure: capacity-slot scatter (exact; overflow -> spill list)
// ---------------------------------------------------------------------------
__global__ void zero_cnt_kernel() {
    const int i = blockIdx.x * 1024 + threadIdx.x;
    if (i < NN) g_cnt[i] = 0;
    if (i == 0) g_spill_cnt = 0;
}
__global__ __launch_bounds__(256) void scatter_kernel(const int* __restrict__ ei) {
    const int idx = blockIdx.x * 256 + threadIdx.x;  // 2 edges/thread
    const int2 r = reinterpret_cast<const int2*>(ei)[idx];
    const int2 c = reinterpret_cast<const int2*>(ei + EE)[idx];
    int pos = atomicAdd(&g_cnt[r.x], 1);
    if (pos < CAP) g_col[(size_t)r.x * CAP + pos] = c.x;
    else { int s = atomicAdd(&g_spill_cnt, 1); g_spill[s] = make_int2(r.x, c.x); }
    pos = atomicAdd(&g_cnt[r.y], 1);
    if (pos < CAP) g_col[(size_t)r.y * CAP + pos] = c.y;
    else { int s = atomicAdd(&g_spill_cnt, 1); g_spill[s] = make_int2(r.y, c.y); }
}

// ---------------------------------------------------------------------------
// agg[n] = sum_{neighbors} |h[n] - h[c]|   (warp/node, MLP=8 gather)
// ---------------------------------------------------------------------------
__global__ __launch_bounds__(512) void agg_kernel() {
    const int node = blockIdx.x * 16 + (threadIdx.x >> 5);
    const int lane = threadIdx.x & 31;
    const float* __restrict__ h = g_h;
    const float4 hi = *reinterpret_cast<const float4*>(h + (size_t)node * HD + lane * 4);
    float4 acc = make_float4(0.f, 0.f, 0.f, 0.f);
    const int deg = min(g_cnt[node], CAP);
    const int* base = g_col + (size_t)node * CAP;
    int e = 0;
    for (; e + 8 <= deg; e += 8) {
        const int4 ia = *reinterpret_cast<const int4*>(base + e);
        const int4 ib = *reinterpret_cast<const int4*>(base + e + 4);
        const float4 v0 = *reinterpret_cast<const float4*>(h + (size_t)ia.x * HD + lane * 4);
        const float4 v1 = *reinterpret_cast<const float4*>(h + (size_t)ia.y * HD + lane * 4);
        const float4 v2 = *reinterpret_cast<const float4*>(h + (size_t)ia.z * HD + lane * 4);
        const float4 v3 = *reinterpret_cast<const float4*>(h + (size_t)ia.w * HD + lane * 4);
        const float4 v4 = *reinterpret_cast<const float4*>(h + (size_t)ib.x * HD + lane * 4);
        const float4 v5 = *reinterpret_cast<const float4*>(h + (size_t)ib.y * HD + lane * 4);
        const float4 v6 = *reinterpret_cast<const float4*>(h + (size_t)ib.z * HD + lane * 4);
        const float4 v7 = *reinterpret_cast<const float4*>(h + (size_t)ib.w * HD + lane * 4);
        acc.x += fabsf(hi.x - v0.x) + fabsf(hi.x - v1.x) + fabsf(hi.x - v2.x) + fabsf(hi.x - v3.x)
               + fabsf(hi.x - v4.x) + fabsf(hi.x - v5.x) + fabsf(hi.x - v6.x) + fabsf(hi.x - v7.x);
        acc.y += fabsf(hi.y - v0.y) + fabsf(hi.y - v1.y) + fabsf(hi.y - v2.y) + fabsf(hi.y - v3.y)
               + fabsf(hi.y - v4.y) + fabsf(hi.y - v5.y) + fabsf(hi.y - v6.y) + fabsf(hi.y - v7.y);
        acc.z += fabsf(hi.z - v0.z) + fabsf(hi.z - v1.z) + fabsf(hi.z - v2.z) + fabsf(hi.z - v3.z)
               + fabsf(hi.z - v4.z) + fabsf(hi.z - v5.z) + fabsf(hi.z - v6.z) + fabsf(hi.z - v7.z);
        acc.w += fabsf(hi.w - v0.w) + fabsf(hi.w - v1.w) + fabsf(hi.w - v2.w) + fabsf(hi.w - v3.w)
               + fabsf(hi.w - v4.w) + fabsf(hi.w - v5.w) + fabsf(hi.w - v6.w) + fabsf(hi.w - v7.w);
    }
    for (; e < deg; ++e) {
        const int c0 = base[e];
        const float4 a = *reinterpret_cast<const float4*>(h + (size_t)c0 * HD + lane * 4);
        acc.x += fabsf(hi.x - a.x);
        acc.y += fabsf(hi.y - a.y);
        acc.z += fabsf(hi.z - a.z);
        acc.w += fabsf(hi.w - a.w);
    }
    *reinterpret_cast<float4*>(g_agg + (size_t)node * HD + lane * 4) = acc;
}

// Exact fix-up for capacity overflow (normally zero work)
__global__ __launch_bounds__(256) void spill_kernel() {
    const int gw = blockIdx.x * 8 + (threadIdx.x >> 5);
    const int lane = threadIdx.x & 31;
    const int n = g_spill_cnt;
    for (int s = gw; s < n; s += 64) {
        const int2 e = g_spill[s];
        const float4 a = *reinterpret_cast<const float4*>(g_h + (size_t)e.x * HD + lane * 4);
        const float4 b = *reinterpret_cast<const float4*>(g_h + (size_t)e.y * HD + lane * 4);
        float* p = g_agg + (size_t)e.x * HD + lane * 4;
        asm volatile("red.global.add.v4.f32 [%0], {%1,%2,%3,%4};"
                     :: "l"(p), "f"(fabsf(a.x - b.x)), "f"(fabsf(a.y - b.y)),
                        "f"(fabsf(a.z - b.z)), "f"(fabsf(a.w - b.w)) : "memory");
    }
}

// ---------------------------------------------------------------------------
// Fused node kernel — common path: zero smem, zero block syncs.
//   hw  = relu([h,agg] @ Wd^T + bd)          (k-major weights from global)
//   tau = softplus(hw @ Wt^T + bt)           (regs + warp butterfly)
//   per-WARP GRU skip; exact per-warp GRU fallback via g_hw scratch
//   layer 2: fused out = h_new @ Wo^T + bo (h not stored)
// ---------------------------------------------------------------------------
__global__ __launch_bounds__(128, 4) void node_kernel(
    int layer, const float* __restrict__ bd,
    const float* __restrict__ Wt, const float* __restrict__ bt,
    const float* __restrict__ bih, const float* __restrict__ bhh,
    const float* __restrict__ Wo, const float* __restrict__ bo,
    float* __restrict__ out, float* __restrict__ tau_out) {
    const int node0 = blockIdx.x * 32;
    const int lane = threadIdx.x & 31;
    const int i0 = (threadIdx.x >> 5) * 8, j0 = lane * 4;
    const float* WdTl = g_WdT + layer * 32768;
    const float* Ah = g_h + (size_t)node0 * HD;
    const float* Aa = g_agg + (size_t)node0 * HD;

    // ---- phase 1: hw = relu([h,agg] @ Wd^T + bd) ----
    ull acc[8][2];
    {
        const float4 b4 = *reinterpret_cast<const float4*>(bd + j0);
        const ull b0 = pack2(b4.x, b4.y), b1 = pack2(b4.z, b4.w);
#pragma unroll
        for (int u = 0; u < 8; ++u) { acc[u][0] = b0; acc[u][1] = b1; }
    }
#pragma unroll 1
    for (int kt = 0; kt < 4; ++kt)
        mma8g(acc, WdTl + kt * 4096, Ah, HD, kt * 32, i0, j0);
#pragma unroll 1
    for (int kt = 0; kt < 4; ++kt)
        mma8g(acc, WdTl + 16384 + kt * 4096, Aa, HD, kt * 32, i0, j0);

    float hw[8][4];
#pragma unroll
    for (int u = 0; u < 8; ++u) {
        float a0, a1, a2, a3;
        unpack2(a0, a1, acc[u][0]);
        unpack2(a2, a3, acc[u][1]);
        hw[u][0] = fmaxf(a0, 0.f); hw[u][1] = fmaxf(a1, 0.f);
        hw[u][2] = fmaxf(a2, 0.f); hw[u][3] = fmaxf(a3, 0.f);
    }

    // ---- phase 2: tau (regs + butterfly; lane0 value broadcast for uniformity) ----
    const float4 wt4 = *reinterpret_cast<const float4*>(Wt + j0);
    const float bt0 = bt[0];
    int mskbits = 0;
#pragma unroll
    for (int u = 0; u < 8; ++u) {
        float p = hw[u][0] * wt4.x + hw[u][1] * wt4.y +
                  hw[u][2] * wt4.z + hw[u][3] * wt4.w;
#pragma unroll
        for (int o = 16; o > 0; o >>= 1) p += __shfl_xor_sync(0xffffffffu, p, o);
        p = __shfl_sync(0xffffffffu, p, 0);
        const float tv = softplusf_(p + bt0);
        if (tau_out && lane == 0) tau_out[node0 + i0 + u] = tv;
        if (tv < 0.005f) mskbits |= 1 << u;
    }
    const bool rare = __any_sync(0xffffffffu, mskbits != 0);  // uniform: mskbits uniform

    if (!rare) {
        if (out) {
            const float4 wo0 = *reinterpret_cast<const float4*>(Wo + j0);
            const float4 wo1 = *reinterpret_cast<const float4*>(Wo + 128 + j0);
            const float bo0 = bo[0], bo1 = bo[1];
#pragma unroll
            for (int u = 0; u < 8; ++u) {
                float p0 = hw[u][0] * wo0.x + hw[u][1] * wo0.y + hw[u][2] * wo0.z + hw[u][3] * wo0.w;
                float p1 = hw[u][0] * wo1.x + hw[u][1] * wo1.y + hw[u][2] * wo1.z + hw[u][3] * wo1.w;
#pragma unroll
                for (int o = 16; o > 0; o >>= 1) {
                    p0 += __shfl_xor_sync(0xffffffffu, p0, o);
                    p1 += __shfl_xor_sync(0xffffffffu, p1, o);
                }
                if (lane == 0)
                    *reinterpret_cast<float2*>(out + (size_t)(node0 + i0 + u) * 2) =
                        make_float2(p0 + bo0, p1 + bo1);
            }
        } else {
#pragma unroll
            for (int u = 0; u < 8; ++u)
                *reinterpret_cast<float4*>(g_h + (size_t)(node0 + i0 + u) * HD + j0) =
                    make_float4(hw[u][0], hw[u][1], hw[u][2], hw[u][3]);
        }
        return;
    }

    // ---- rare path: exact per-warp masked GRU(agg, hw) ----
    const float* Ahw = g_hw + (size_t)node0 * HD;
#pragma unroll
    for (int u = 0; u < 8; ++u)
        *reinterpret_cast<float4*>(g_hw + (size_t)(node0 + i0 + u) * HD + j0) =
            make_float4(hw[u][0], hw[u][1], hw[u][2], hw[u][3]);
    __threadfence_block();
    __syncwarp();

    // r gate
    float r_[8][4];
    {
        ull ga[8][2];
        const float4 bi = *reinterpret_cast<const float4*>(bih + j0);
        const float4 bh = *reinterpret_cast<const float4*>(bhh + j0);
        const ull b0 = pack2(bi.x + bh.x, bi.y + bh.y);
        const ull b1 = pack2(bi.z + bh.z, bi.w + bh.w);
#pragma unroll
        for (int u = 0; u < 8; ++u) { ga[u][0] = b0; ga[u][1] = b1; }
#pragma unroll 1
        for (int kt = 0; kt < 4; ++kt)
            mma8g(ga, g_WihT + kt * 4096, Aa, HD, kt * 32, i0, j0);
#pragma unroll 1
        for (int kt = 0; kt < 4; ++kt)
            mma8g(ga, g_WhhT + kt * 4096, Ahw, HD, kt * 32, i0, j0);
#pragma unroll
        for (int u = 0; u < 8; ++u) {
            float a0, a1, a2, a3;
            unpack2(a0, a1, ga[u][0]); unpack2(a2, a3, ga[u][1]);
            r_[u][0] = sigmoidf_(a0); r_[u][1] = sigmoidf_(a1);
            r_[u][2] = sigmoidf_(a2); r_[u][3] = sigmoidf_(a3);
        }
    }
    // rh = r * (bhh_n + hw@Whhn^T)
    float rh[8][4];
    {
        ull hn[8][2];
        const float4 bh = *reinterpret_cast<const float4*>(bhh + 256 + j0);
        const ull b0 = pack2(bh.x, bh.y), b1 = pack2(bh.z, bh.w);
#pragma unroll
        for (int u = 0; u < 8; ++u) { hn[u][0] = b0; hn[u][1] = b1; }
#pragma unroll 1
        for (int kt = 0; kt < 4; ++kt)
            mma8g(hn, g_WhhT + 32768 + kt * 4096, Ahw, HD, kt * 32, i0, j0);
#pragma unroll
        for (int u = 0; u < 8; ++u) {
            float a0, a1, a2, a3;
            unpack2(a0, a1, hn[u][0]); unpack2(a2, a3, hn[u][1]);
            rh[u][0] = r_[u][0] * a0; rh[u][1] = r_[u][1] * a1;
            rh[u][2] = r_[u][2] * a2; rh[u][3] = r_[u][3] * a3;
        }
    }
    // n = tanh(bih_n + agg@Wihn^T + rh)
    float n_[8][4];
    {
        ull in_[8][2];
        const float4 bi = *reinterpret_cast<const float4*>(bih + 256 + j0);
        const ull b0 = pack2(bi.x, bi.y), b1 = pack2(bi.z, bi.w);
#pragma unroll
        for (int u = 0; u < 8; ++u) { in_[u][0] = b0; in_[u][1] = b1; }
#pragma unroll 1
        for (int kt = 0; kt < 4; ++kt)
            mma8g(in_, g_WihT + 32768 + kt * 4096, Aa, HD, kt * 32, i0, j0);
#pragma unroll
        for (int u = 0; u < 8; ++u) {
            float a0, a1, a2, a3;
            unpack2(a0, a1, in_[u][0]); unpack2(a2, a3, in_[u][1]);
            n_[u][0] = tanhf(a0 + rh[u][0]); n_[u][1] = tanhf(a1 + rh[u][1]);
            n_[u][2] = tanhf(a2 + rh[u][2]); n_[u][3] = tanhf(a3 + rh[u][3]);
        }
    }
    // z gate + combine + output
    {
        ull gz[8][2];
        const float4 bi = *reinterpret_cast<const float4*>(bih + 128 + j0);
        const float4 bh = *reinterpret_cast<const float4*>(bhh + 128 + j0);
        const ull b0 = pack2(bi.x + bh.x, bi.y + bh.y);
        const ull b1 = pack2(bi.z + bh.z, bi.w + bh.w);
#pragma unroll
        for (int u = 0; u < 8; ++u) { gz[u][0] = b0; gz[u][1] = b1; }
#pragma unroll 1
        for (int kt = 0; kt < 4; ++kt)
            mma8g(gz, g_WihT + 16384 + kt * 4096, Aa, HD, kt * 32, i0, j0);
#pragma unroll 1
        for (int kt = 0; kt < 4; ++kt)
            mma8g(gz, g_WhhT + 16384 + kt * 4096, Ahw, HD, kt * 32, i0, j0);

        const float4 wo0 = out ? *reinterpret_cast<const float4*>(Wo + j0) : make_float4(0,0,0,0);
        const float4 wo1 = out ? *reinterpret_cast<const float4*>(Wo + 128 + j0) : make_float4(0,0,0,0);
        const float bo0 = out ? bo[0] : 0.f, bo1 = out ? bo[1] : 0.f;
#pragma unroll
        for (int u = 0; u < 8; ++u) {
            float a0, a1, a2, a3;
            unpack2(a0, a1, gz[u][0]); unpack2(a2, a3, gz[u][1]);
            const float zv[4] = {sigmoidf_(a0), sigmoidf_(a1), sigmoidf_(a2), sigmoidf_(a3)};
            const bool msk = (mskbits >> u) & 1;
            float ov[4];
#pragma unroll
            for (int v = 0; v < 4; ++v) {
                const float hn = (1.0f - zv[v]) * n_[u][v] + zv[v] * hw[u][v];
                ov[v] = msk ? hn : hw[u][v];
            }
            if (out) {
                float p0 = ov[0] * wo0.x + ov[1] * wo0.y + ov[2] * wo0.z + ov[3] * wo0.w;
                float p1 = ov[0] * wo1.x + ov[1] * wo1.y + ov[2] * wo1.z + ov[3] * wo1.w;
#pragma unroll
                for (int o = 16; o > 0; o >>= 1) {
                    p0 += __shfl_xor_sync(0xffffffffu, p0, o);
                    p1 += __shfl_xor_sync(0xffffffffu, p1, o);
                }
                if (lane == 0)
                    *reinterpret_cast<float2*>(out + (size_t)(node0 + i0 + u) * 2) =
                        make_float2(p0 + bo0, p1 + bo1);
            } else {
                *reinterpret_cast<float4*>(g_h + (size_t)(node0 + i0 + u) * HD + j0) =
                    make_float4(ov[0], ov[1], ov[2], ov[3]);
            }
        }
    }
}

// ---------------------------------------------------------------------------
extern "C" void kernel_launch(void* const* d_in, const int* in_sizes, int n_in,
                              void* d_out, int out_size) {
    const float* x    = (const float*)d_in[0];
    const int*   ei   = (const int*)d_in[1];   // int32 (JAX x64-disabled)
    const float* W_in = (const float*)d_in[2];
    const float* b_in = (const float*)d_in[3];
    const float* Wd   = (const float*)d_in[4];  (void)Wd;
    const float* bd   = (const float*)d_in[5];
    const float* Wt   = (const float*)d_in[6];
    const float* bt   = (const float*)d_in[7];
    const float* Wih  = (const float*)d_in[8];
    const float* Whh  = (const float*)d_in[9];
    const float* bih  = (const float*)d_in[10];
    const float* bhh  = (const float*)d_in[11];
    const float* Wo   = (const float*)d_in[12];
    const float* bo   = (const float*)d_in[13];

    float* out = (float*)d_out;
    float* tau_out = (out_size >= NN * 3) ? out + (size_t)NN * 2 : nullptr;

    // edge slots (layer-invariant)
    zero_cnt_kernel<<<(NN + 1023) / 1024, 1024>>>();
    scatter_kernel<<<EE / 512, 256>>>(ei);

    // weight transposes (k-major)
    t_win_kernel<<<64, 256>>>(W_in);
    t_wd_kernel<<<256, 256>>>((const float*)d_in[4]);
    t_wih_kernel<<<192, 256>>>(Wih);
    t_whh_kernel<<<192, 256>>>(Whh);

    in_gemm_kernel<<<NN / 32, 128>>>(x, b_in);

    for (int l = 0; l < 2; ++l) {
        agg_kernel<<<NN / 16, 512>>>();
        spill_kernel<<<8, 256>>>();
        node_kernel<<<NN / 32, 128>>>(
            l, bd + (size_t)l * HD, Wt, bt, bih, bhh, Wo, bo,
            (l == 1) ? out : nullptr, (l == 1) ? tau_out : nullptr);
    }
}